// round 3
// baseline (speedup 1.0000x reference)
#include <cuda_runtime.h>
#include <math.h>

#define BSZ  8
#define SEQ  2048
#define DM   512
#define DAUX 64
#define NEG_HUGE (-3.402823466e38f)

// Static scratch (no allocation allowed in kernel_launch)
__device__ float g_q[(size_t)BSZ*SEQ*DM];
__device__ float g_k[(size_t)BSZ*SEQ*DM];
__device__ float g_v[(size_t)BSZ*SEQ*DM];
__device__ float g_s[(size_t)BSZ*SEQ*SEQ];

// ---------------------------------------------------------------------------
// QKV projection: out[m,n] = sum_k x[m,k] * W[n,k] + bias[n]
// (A @ B^T with both row-major). 64x64 tile, K-chunk 16, 256 thr, 4x4 micro.
// grid: (DM/64, (BSZ*SEQ)/64, 3)   z selects q/k/v
// ---------------------------------------------------------------------------
__global__ __launch_bounds__(256) void qkv_kernel(
    const float* __restrict__ x,
    const float* __restrict__ Wq, const float* __restrict__ bq,
    const float* __restrict__ Wk, const float* __restrict__ bk,
    const float* __restrict__ Wv, const float* __restrict__ bv)
{
    const float* W; const float* bias; float* out;
    if (blockIdx.z == 0)      { W = Wq; bias = bq; out = g_q; }
    else if (blockIdx.z == 1) { W = Wk; bias = bk; out = g_k; }
    else                      { W = Wv; bias = bv; out = g_v; }

    const int m0 = blockIdx.y * 64;
    const int n0 = blockIdx.x * 64;

    __shared__ float As[16][65];   // As[k][m]
    __shared__ float Bs[16][65];   // Bs[k][n]

    const int tid = threadIdx.x;
    const int tx = tid & 15, ty = tid >> 4;
    const int lr = tid >> 4, lc = tid & 15;

    float acc[4][4] = {};

    for (int k0 = 0; k0 < DM; k0 += 16) {
        #pragma unroll
        for (int i = 0; i < 4; i++) {
            int r = lr + i*16;
            As[lc][r] = x[(size_t)(m0 + r)*DM + k0 + lc];
            Bs[lc][r] = W[(size_t)(n0 + r)*DM + k0 + lc];
        }
        __syncthreads();
        #pragma unroll
        for (int kk = 0; kk < 16; kk++) {
            float a[4], b[4];
            #pragma unroll
            for (int i = 0; i < 4; i++) a[i] = As[kk][ty + i*16];
            #pragma unroll
            for (int j = 0; j < 4; j++) b[j] = Bs[kk][tx + j*16];
            #pragma unroll
            for (int i = 0; i < 4; i++)
                #pragma unroll
                for (int j = 0; j < 4; j++)
                    acc[i][j] += a[i]*b[j];
        }
        __syncthreads();
    }

    #pragma unroll
    for (int i = 0; i < 4; i++) {
        int m = m0 + ty + i*16;
        #pragma unroll
        for (int j = 0; j < 4; j++) {
            int n = n0 + tx + j*16;
            out[(size_t)m*DM + n] = acc[i][j] + bias[n];
        }
    }
}

// ---------------------------------------------------------------------------
// scores[b,n,m] = merge(q.k^T/sqrt(D), qa.ka^T/sqrt(Daux)) with adjacency mask
// grid: (SEQ/64 key tiles, SEQ/64 query tiles, BSZ)
// ---------------------------------------------------------------------------
__global__ __launch_bounds__(256) void scores_kernel(
    const float* __restrict__ qa, const float* __restrict__ ka,
    const int*   __restrict__ adj,
    const float* __restrict__ p_mc, const float* __restrict__ p_thr)
{
    const int b  = blockIdx.z;
    const int n0 = blockIdx.y * 64;   // query rows
    const int m0 = blockIdx.x * 64;   // key rows

    const float* Q  = g_q + (size_t)b*SEQ*DM;
    const float* K  = g_k + (size_t)b*SEQ*DM;
    const float* QA = qa  + (size_t)b*SEQ*DAUX;
    const float* KA = ka  + (size_t)b*SEQ*DAUX;

    __shared__ float As[16][65];
    __shared__ float Bs[16][65];

    const int tid = threadIdx.x;
    const int tx = tid & 15, ty = tid >> 4;
    const int lr = tid >> 4, lc = tid & 15;

    float acc[4][4] = {};
    for (int k0 = 0; k0 < DM; k0 += 16) {
        #pragma unroll
        for (int i = 0; i < 4; i++) {
            int r = lr + i*16;
            As[lc][r] = Q[(size_t)(n0 + r)*DM + k0 + lc];
            Bs[lc][r] = K[(size_t)(m0 + r)*DM + k0 + lc];
        }
        __syncthreads();
        #pragma unroll
        for (int kk = 0; kk < 16; kk++) {
            float a[4], bb[4];
            #pragma unroll
            for (int i = 0; i < 4; i++) a[i] = As[kk][ty + i*16];
            #pragma unroll
            for (int j = 0; j < 4; j++) bb[j] = Bs[kk][tx + j*16];
            #pragma unroll
            for (int i = 0; i < 4; i++)
                #pragma unroll
                for (int j = 0; j < 4; j++)
                    acc[i][j] += a[i]*bb[j];
        }
        __syncthreads();
    }

    float accaux[4][4] = {};
    for (int k0 = 0; k0 < DAUX; k0 += 16) {
        #pragma unroll
        for (int i = 0; i < 4; i++) {
            int r = lr + i*16;
            As[lc][r] = QA[(size_t)(n0 + r)*DAUX + k0 + lc];
            Bs[lc][r] = KA[(size_t)(m0 + r)*DAUX + k0 + lc];
        }
        __syncthreads();
        #pragma unroll
        for (int kk = 0; kk < 16; kk++) {
            float a[4], bb[4];
            #pragma unroll
            for (int i = 0; i < 4; i++) a[i] = As[kk][ty + i*16];
            #pragma unroll
            for (int j = 0; j < 4; j++) bb[j] = Bs[kk][tx + j*16];
            #pragma unroll
            for (int i = 0; i < 4; i++)
                #pragma unroll
                for (int j = 0; j < 4; j++)
                    accaux[i][j] += a[i]*bb[j];
        }
        __syncthreads();
    }

    const float mc  = *p_mc;
    const float thr = *p_thr;
    const float inv_s    = 1.0f / sqrtf((float)DM);
    const float inv_saux = 1.0f / sqrtf((float)DAUX);

    #pragma unroll
    for (int i = 0; i < 4; i++) {
        int n = n0 + ty + i*16;
        #pragma unroll
        for (int j = 0; j < 4; j++) {
            int m = m0 + tx + j*16;
            float s  = acc[i][j]    * inv_s;
            float sa = accaux[i][j] * inv_saux;
            if ((sa != 0.0f) && (s > thr))
                s = (1.0f - mc)*s + mc*sa;
            size_t idx = ((size_t)b*SEQ + n)*SEQ + m;
            if (adj[idx] == 0) s = NEG_HUGE;
            g_s[idx] = s;
        }
    }
}

// ---------------------------------------------------------------------------
// Row softmax over g_s rows (length SEQ). One CTA (256 thr) per row.
// ---------------------------------------------------------------------------
__global__ __launch_bounds__(256) void softmax_kernel()
{
    const size_t row = blockIdx.x;
    float* s = g_s + row * SEQ;
    const int tid = threadIdx.x;

    float v[8];
    float mx = -INFINITY;
    #pragma unroll
    for (int i = 0; i < 8; i++) {
        v[i] = s[tid + i*256];
        mx = fmaxf(mx, v[i]);
    }

    __shared__ float red[8];
    // block max
    #pragma unroll
    for (int o = 16; o; o >>= 1) mx = fmaxf(mx, __shfl_xor_sync(0xffffffffu, mx, o));
    if ((tid & 31) == 0) red[tid >> 5] = mx;
    __syncthreads();
    if (tid < 32) {
        float t = (tid < 8) ? red[tid] : -INFINITY;
        #pragma unroll
        for (int o = 4; o; o >>= 1) t = fmaxf(t, __shfl_xor_sync(0xffffffffu, t, o));
        if (tid == 0) red[0] = t;
    }
    __syncthreads();
    mx = red[0];
    __syncthreads();

    float sum = 0.0f;
    #pragma unroll
    for (int i = 0; i < 8; i++) {
        v[i] = expf(v[i] - mx);
        sum += v[i];
    }
    // block sum
    #pragma unroll
    for (int o = 16; o; o >>= 1) sum += __shfl_xor_sync(0xffffffffu, sum, o);
    if ((tid & 31) == 0) red[tid >> 5] = sum;
    __syncthreads();
    if (tid < 32) {
        float t = (tid < 8) ? red[tid] : 0.0f;
        #pragma unroll
        for (int o = 4; o; o >>= 1) t += __shfl_xor_sync(0xffffffffu, t, o);
        if (tid == 0) red[0] = t;
    }
    __syncthreads();
    const float inv = 1.0f / red[0];

    #pragma unroll
    for (int i = 0; i < 8; i++)
        s[tid + i*256] = v[i] * inv;
}

// ---------------------------------------------------------------------------
// out[b,n,d] = sum_m weights[b,n,m] * v[b,m,d]   (A @ B, both row-major)
// grid: (DM/64, SEQ/64, BSZ)
// ---------------------------------------------------------------------------
__global__ __launch_bounds__(256) void av_kernel(float* __restrict__ out)
{
    const int b  = blockIdx.z;
    const int n0 = blockIdx.y * 64;
    const int d0 = blockIdx.x * 64;

    const float* Wt = g_s + (size_t)b*SEQ*SEQ;
    const float* V  = g_v + (size_t)b*SEQ*DM;

    __shared__ float As[16][65];   // As[k][row]
    __shared__ float Bs[16][65];   // Bs[k][col]

    const int tid = threadIdx.x;
    const int tx = tid & 15, ty = tid >> 4;
    const int lr = tid >> 4, lc = tid & 15;
    const int bc = tid & 63;   // col 0..63
    const int bk = tid >> 6;   // 0..3

    float acc[4][4] = {};

    for (int k0 = 0; k0 < SEQ; k0 += 16) {
        #pragma unroll
        for (int i = 0; i < 4; i++)
            As[lc][lr + i*16] = Wt[(size_t)(n0 + lr + i*16)*SEQ + k0 + lc];
        #pragma unroll
        for (int i = 0; i < 4; i++)
            Bs[bk + i*4][bc] = V[(size_t)(k0 + bk + i*4)*DM + d0 + bc];
        __syncthreads();
        #pragma unroll
        for (int kk = 0; kk < 16; kk++) {
            float a[4], bb[4];
            #pragma unroll
            for (int i = 0; i < 4; i++) a[i] = As[kk][ty + i*16];
            #pragma unroll
            for (int j = 0; j < 4; j++) bb[j] = Bs[kk][tx + j*16];
            #pragma unroll
            for (int i = 0; i < 4; i++)
                #pragma unroll
                for (int j = 0; j < 4; j++)
                    acc[i][j] += a[i]*bb[j];
        }
        __syncthreads();
    }

    #pragma unroll
    for (int i = 0; i < 4; i++) {
        int n = n0 + ty + i*16;
        #pragma unroll
        for (int j = 0; j < 4; j++) {
            int d = d0 + tx + j*16;
            out[((size_t)b*SEQ + n)*DM + d] = acc[i][j];
        }
    }
}

// ---------------------------------------------------------------------------
extern "C" void kernel_launch(void* const* d_in, const int* in_sizes, int n_in,
                              void* d_out, int out_size)
{
    const float* x   = (const float*)d_in[0];
    const float* qa  = (const float*)d_in[1];
    const float* ka  = (const float*)d_in[2];
    const int*   adj = (const int*)d_in[3];
    const float* mc  = (const float*)d_in[4];
    const float* Wq  = (const float*)d_in[5];
    const float* bq  = (const float*)d_in[6];
    const float* Wk  = (const float*)d_in[7];
    const float* bk  = (const float*)d_in[8];
    const float* Wv  = (const float*)d_in[9];
    const float* bv  = (const float*)d_in[10];
    const float* thr = (const float*)d_in[11];
    float* out = (float*)d_out;

    dim3 t(256);
    qkv_kernel   <<<dim3(DM/64, (BSZ*SEQ)/64, 3),  t>>>(x, Wq, bq, Wk, bk, Wv, bv);
    scores_kernel<<<dim3(SEQ/64, SEQ/64, BSZ),     t>>>(qa, ka, adj, mc, thr);
    softmax_kernel<<<dim3(BSZ*SEQ),                t>>>();
    av_kernel    <<<dim3(DM/64, SEQ/64, BSZ),      t>>>(out);
}

// round 5
// speedup vs baseline: 2.1111x; 2.1111x over previous
#include <cuda_runtime.h>
#include <cuda_bf16.h>
#include <math.h>
#include <stdint.h>

#define BSZ  8
#define SEQ  2048
#define DM   512
#define DAUX 64
#define NEG_HUGE (-3.402823466e38f)
#define INV_S  0.044194173824159216f
#define INV_SA 0.125f

typedef __nv_bfloat16 bf;

// smem tile geometry: rows of 16 bf16 (32B data) padded to 48B
#define ROWB 48
#define OPSZ (128*ROWB)        // 6144 B per operand tile
#define STAGE (4*OPSZ)         // Ah, Al, Bh, Bl
// 2 stages = 49152 B = 48KB static smem

// -------- static scratch --------
__device__ bf g_xh [(size_t)BSZ*SEQ*DM];
__device__ bf g_xl [(size_t)BSZ*SEQ*DM];
__device__ bf g_Wh [3][DM*DM];
__device__ bf g_Wl [3][DM*DM];
__device__ bf g_qh [(size_t)BSZ*SEQ*DM];
__device__ bf g_ql [(size_t)BSZ*SEQ*DM];
__device__ bf g_kh [(size_t)BSZ*SEQ*DM];
__device__ bf g_kl [(size_t)BSZ*SEQ*DM];
__device__ bf g_vth[(size_t)BSZ*SEQ*DM];   // [b][d][m]
__device__ bf g_vtl[(size_t)BSZ*SEQ*DM];
__device__ bf g_qah[(size_t)BSZ*SEQ*DAUX];
__device__ bf g_qal[(size_t)BSZ*SEQ*DAUX];
__device__ bf g_kah[(size_t)BSZ*SEQ*DAUX];
__device__ bf g_kal[(size_t)BSZ*SEQ*DAUX];
__device__ float g_s[(size_t)BSZ*SEQ*SEQ];
__device__ bf g_ph [(size_t)BSZ*SEQ*SEQ];
__device__ bf g_pl [(size_t)BSZ*SEQ*SEQ];

// -------- helpers --------
__device__ __forceinline__ uint32_t s2u(const void* p){
    uint32_t a;
    asm("{ .reg .u64 t; cvta.to.shared.u64 t, %1; cvt.u32.u64 %0, t; }" : "=r"(a) : "l"(p));
    return a;
}
__device__ __forceinline__ void cp16(uint32_t d, const void* g){
    asm volatile("cp.async.cg.shared.global [%0], [%1], 16;" :: "r"(d), "l"(g) : "memory");
}
#define CP_COMMIT() asm volatile("cp.async.commit_group;" ::: "memory")
#define CP_WAIT0()  asm volatile("cp.async.wait_group 0;" ::: "memory")
#define CP_WAIT1()  asm volatile("cp.async.wait_group 1;" ::: "memory")

__device__ __forceinline__ void ldmx4(uint32_t* r, uint32_t a){
    asm volatile("ldmatrix.sync.aligned.m8n8.x4.shared.b16 {%0,%1,%2,%3}, [%4];"
        : "=r"(r[0]), "=r"(r[1]), "=r"(r[2]), "=r"(r[3]) : "r"(a));
}
__device__ __forceinline__ void mma16816(float* d, const uint32_t* a, uint32_t b0, uint32_t b1){
    asm volatile(
        "mma.sync.aligned.m16n8k16.row.col.f32.bf16.bf16.f32 "
        "{%0,%1,%2,%3}, {%4,%5,%6,%7}, {%8,%9}, {%0,%1,%2,%3};"
        : "+f"(d[0]), "+f"(d[1]), "+f"(d[2]), "+f"(d[3])
        : "r"(a[0]), "r"(a[1]), "r"(a[2]), "r"(a[3]), "r"(b0), "r"(b1));
}
__device__ __forceinline__ void sp(float v, bf& h, bf& l){
    h = __float2bfloat16(v);
    l = __float2bfloat16(v - __bfloat162float(h));
}

// load one K-chunk (16 cols) of 4 operand tiles (Ah, Al, Bh, Bl), 128 rows each
__device__ __forceinline__ void load_chunk(uint32_t stg,
    const bf* __restrict__ Ah, const bf* __restrict__ Al,
    const bf* __restrict__ Bh, const bf* __restrict__ Bl,
    long ld, long koff, int tid)
{
    int r = (tid >> 1) & 127;
    int j = tid & 1;
    long so = (long)r*ld + koff + j*8;
    uint32_t dof = (uint32_t)(r*ROWB + j*16);
    cp16(stg + 0*OPSZ + dof, Ah + so);
    cp16(stg + 1*OPSZ + dof, Al + so);
    cp16(stg + 2*OPSZ + dof, Bh + so);
    cp16(stg + 3*OPSZ + dof, Bl + so);
}

// one K=16 chunk of 3-pass split MMA; warp tile 32(M) x 64(N)
__device__ __forceinline__ void do_chunk(uint32_t stg, float (*acc)[8][4],
                                         int lane, int wm, int wn)
{
    uint32_t ah[2][4], al[2][4], bh[4][4], bl[4][4];
    int arow = lane & 15, asel = (lane >> 4) * 16;
    #pragma unroll
    for (int i = 0; i < 2; i++) {
        uint32_t ra = stg + (wm*32 + i*16 + arow)*ROWB + asel;
        ldmx4(ah[i], ra);
        ldmx4(al[i], ra + OPSZ);
    }
    int brow = ((lane >> 4) << 3) + (lane & 7), bsel = ((lane >> 3) & 1) * 16;
    #pragma unroll
    for (int jt = 0; jt < 4; jt++) {
        uint32_t rb = stg + 2*OPSZ + (wn*64 + jt*16 + brow)*ROWB + bsel;
        ldmx4(bh[jt], rb);
        ldmx4(bl[jt], rb + OPSZ);
    }
    #pragma unroll
    for (int i = 0; i < 2; i++)
        #pragma unroll
        for (int j = 0; j < 8; j++) {
            int jt = j >> 1, o = (j & 1) * 2;
            mma16816(acc[i][j], ah[i], bh[jt][o], bh[jt][o+1]);
            mma16816(acc[i][j], ah[i], bl[jt][o], bl[jt][o+1]);
            mma16816(acc[i][j], al[i], bh[jt][o], bh[jt][o+1]);
        }
}

// ======================= QKV =======================
// grid (DM/128=4, 16384/128=128, 3), 256 thr
__global__ __launch_bounds__(256, 1) void qkv_mma(
    const float* __restrict__ bq, const float* __restrict__ bk,
    const float* __restrict__ bv)
{
    __shared__ __align__(16) unsigned char smem[2*STAGE];
    uint32_t sb = s2u(smem);
    int tid = threadIdx.x, lane = tid & 31, w = tid >> 5, wm = w & 3, wn = w >> 2;
    const int z = blockIdx.z, m0 = blockIdx.y*128, n0 = blockIdx.x*128;
    const bf *Ah = g_xh + (size_t)m0*DM, *Al = g_xl + (size_t)m0*DM;
    const bf *Bh = g_Wh[z] + (size_t)n0*DM, *Bl = g_Wl[z] + (size_t)n0*DM;

    float acc[2][8][4] = {};
    load_chunk(sb, Ah, Al, Bh, Bl, DM, 0, tid); CP_COMMIT();
    for (int c = 0; c < 32; c++) {
        int s = c & 1;
        if (c + 1 < 32) {
            load_chunk(sb + (s^1)*STAGE, Ah, Al, Bh, Bl, DM, (long)(c+1)*16, tid);
            CP_COMMIT(); CP_WAIT1();
        } else CP_WAIT0();
        __syncthreads();
        do_chunk(sb + s*STAGE, acc, lane, wm, wn);
        __syncthreads();
    }

    const float* bias = (z==0) ? bq : (z==1) ? bk : bv;
    #pragma unroll
    for (int i = 0; i < 2; i++)
        #pragma unroll
        for (int j = 0; j < 8; j++)
            #pragma unroll
            for (int e = 0; e < 4; e++) {
                int row = m0 + wm*32 + i*16 + (lane>>2) + ((e>>1)<<3);
                int col = n0 + wn*64 + j*8 + ((lane&3)<<1) + (e&1);
                float v = acc[i][j][e] + bias[col];
                bf h, l; sp(v, h, l);
                if (z == 2) {
                    size_t t = ((size_t)(row>>11)*DM + col)*SEQ + (row & (SEQ-1));
                    g_vth[t] = h; g_vtl[t] = l;
                } else if (z == 0) {
                    size_t t = (size_t)row*DM + col; g_qh[t] = h; g_ql[t] = l;
                } else {
                    size_t t = (size_t)row*DM + col; g_kh[t] = h; g_kl[t] = l;
                }
            }
}

// ======================= scores + merge + mask =======================
// grid (SEQ/128=16, SEQ/128=16, BSZ)
__global__ __launch_bounds__(256, 1) void scores_mma(
    const int* __restrict__ adj,
    const float* __restrict__ pmc, const float* __restrict__ pthr)
{
    __shared__ __align__(16) unsigned char smem[2*STAGE];
    uint32_t sb = s2u(smem);
    int tid = threadIdx.x, lane = tid & 31, w = tid >> 5, wm = w & 3, wn = w >> 2;
    const int b = blockIdx.z, q0 = blockIdx.y*128, c0 = blockIdx.x*128;

    const bf *Qh = g_qh + ((size_t)b*SEQ + q0)*DM, *Ql = g_ql + ((size_t)b*SEQ + q0)*DM;
    const bf *Kh = g_kh + ((size_t)b*SEQ + c0)*DM, *Kl = g_kl + ((size_t)b*SEQ + c0)*DM;
    const bf *QAh = g_qah + ((size_t)b*SEQ + q0)*DAUX, *QAl = g_qal + ((size_t)b*SEQ + q0)*DAUX;
    const bf *KAh = g_kah + ((size_t)b*SEQ + c0)*DAUX, *KAl = g_kal + ((size_t)b*SEQ + c0)*DAUX;

    float acc[2][8][4] = {};
    float acx[2][8][4] = {};

    const int NC = 36;  // 32 main + 4 aux
    load_chunk(sb, Qh, Ql, Kh, Kl, DM, 0, tid); CP_COMMIT();
    for (int c = 0; c < NC; c++) {
        int s = c & 1;
        if (c + 1 < NC) {
            int n = c + 1;
            if (n < 32)
                load_chunk(sb + (s^1)*STAGE, Qh, Ql, Kh, Kl, DM, (long)n*16, tid);
            else
                load_chunk(sb + (s^1)*STAGE, QAh, QAl, KAh, KAl, DAUX, (long)(n-32)*16, tid);
            CP_COMMIT(); CP_WAIT1();
        } else CP_WAIT0();
        __syncthreads();
        do_chunk(sb + s*STAGE, (c < 32) ? acc : acx, lane, wm, wn);
        __syncthreads();
    }

    const float mc = *pmc, thr = *pthr;
    #pragma unroll
    for (int i = 0; i < 2; i++)
        #pragma unroll
        for (int j = 0; j < 8; j++)
            #pragma unroll
            for (int e = 0; e < 4; e++) {
                int n = q0 + wm*32 + i*16 + (lane>>2) + ((e>>1)<<3);
                int m = c0 + wn*64 + j*8 + ((lane&3)<<1) + (e&1);
                float sv = acc[i][j][e] * INV_S;
                float sa = acx[i][j][e] * INV_SA;
                if ((sa != 0.0f) && (sv > thr)) sv = (1.0f - mc)*sv + mc*sa;
                size_t idx = ((size_t)b*SEQ + n)*SEQ + m;
                if (adj[idx] == 0) sv = NEG_HUGE;
                g_s[idx] = sv;
            }
}

// ======================= AV =======================
// grid (DM/128=4, SEQ/128=16, BSZ)
__global__ __launch_bounds__(256, 1) void av_mma(float* __restrict__ out)
{
    __shared__ __align__(16) unsigned char smem[2*STAGE];
    uint32_t sb = s2u(smem);
    int tid = threadIdx.x, lane = tid & 31, w = tid >> 5, wm = w & 3, wn = w >> 2;
    const int b = blockIdx.z, n0 = blockIdx.y*128, d0 = blockIdx.x*128;

    const bf *Ah = g_ph + ((size_t)b*SEQ + n0)*SEQ, *Al = g_pl + ((size_t)b*SEQ + n0)*SEQ;
    const bf *Bh = g_vth + ((size_t)b*DM + d0)*SEQ, *Bl = g_vtl + ((size_t)b*DM + d0)*SEQ;

    float acc[2][8][4] = {};
    const int NC = SEQ/16;  // 128
    load_chunk(sb, Ah, Al, Bh, Bl, SEQ, 0, tid); CP_COMMIT();
    for (int c = 0; c < NC; c++) {
        int s = c & 1;
        if (c + 1 < NC) {
            load_chunk(sb + (s^1)*STAGE, Ah, Al, Bh, Bl, SEQ, (long)(c+1)*16, tid);
            CP_COMMIT(); CP_WAIT1();
        } else CP_WAIT0();
        __syncthreads();
        do_chunk(sb + s*STAGE, acc, lane, wm, wn);
        __syncthreads();
    }

    #pragma unroll
    for (int i = 0; i < 2; i++)
        #pragma unroll
        for (int j = 0; j < 8; j++)
            #pragma unroll
            for (int e = 0; e < 4; e++) {
                int n = n0 + wm*32 + i*16 + (lane>>2) + ((e>>1)<<3);
                int d = d0 + wn*64 + j*8 + ((lane&3)<<1) + (e&1);
                out[((size_t)b*SEQ + n)*DM + d] = acc[i][j][e];
            }
}

// ======================= softmax (emits bf16 hi/lo weights) ============
__global__ __launch_bounds__(256) void softmax_kernel()
{
    const size_t row = blockIdx.x;
    const float* s = g_s + row*SEQ;
    bf* ph = g_ph + row*SEQ;
    bf* pl = g_pl + row*SEQ;
    const int tid = threadIdx.x;

    float v[8]; float mx = -INFINITY;
    #pragma unroll
    for (int i = 0; i < 8; i++) { v[i] = s[tid + i*256]; mx = fmaxf(mx, v[i]); }
    __shared__ float red[8];
    #pragma unroll
    for (int o = 16; o; o >>= 1) mx = fmaxf(mx, __shfl_xor_sync(~0u, mx, o));
    if ((tid & 31) == 0) red[tid >> 5] = mx;
    __syncthreads();
    if (tid < 32) {
        float t = (tid < 8) ? red[tid] : -INFINITY;
        #pragma unroll
        for (int o = 4; o; o >>= 1) t = fmaxf(t, __shfl_xor_sync(~0u, t, o));
        if (tid == 0) red[0] = t;
    }
    __syncthreads();
    mx = red[0]; __syncthreads();
    float sum = 0.0f;
    #pragma unroll
    for (int i = 0; i < 8; i++) { v[i] = expf(v[i] - mx); sum += v[i]; }
    #pragma unroll
    for (int o = 16; o; o >>= 1) sum += __shfl_xor_sync(~0u, sum, o);
    if ((tid & 31) == 0) red[tid >> 5] = sum;
    __syncthreads();
    if (tid < 32) {
        float t = (tid < 8) ? red[tid] : 0.0f;
        #pragma unroll
        for (int o = 4; o; o >>= 1) t += __shfl_xor_sync(~0u, t, o);
        if (tid == 0) red[0] = t;
    }
    __syncthreads();
    const float inv = 1.0f / red[0];
    #pragma unroll
    for (int i = 0; i < 8; i++) {
        bf h, l; sp(v[i]*inv, h, l);
        ph[tid + i*256] = h; pl[tid + i*256] = l;
    }
}

// ======================= prep: fp32 -> bf16 hi/lo split ================
// which: 0=x, 1..3=Wq/Wk/Wv, 4=query_aux, 5=key_aux
__global__ __launch_bounds__(256) void split_sel(int which,
    const float* __restrict__ src, long n4)
{
    long i = (long)blockIdx.x*256 + threadIdx.x;
    if (i >= n4) return;
    bf *H, *L;
    switch (which) {
        case 0: H = g_xh;    L = g_xl;    break;
        case 1: H = g_Wh[0]; L = g_Wl[0]; break;
        case 2: H = g_Wh[1]; L = g_Wl[1]; break;
        case 3: H = g_Wh[2]; L = g_Wl[2]; break;
        case 4: H = g_qah;   L = g_qal;   break;
        default: H = g_kah;  L = g_kal;   break;
    }
    float4 v = ((const float4*)src)[i];
    bf h, l;
    sp(v.x, h, l); H[i*4+0] = h; L[i*4+0] = l;
    sp(v.y, h, l); H[i*4+1] = h; L[i*4+1] = l;
    sp(v.z, h, l); H[i*4+2] = h; L[i*4+2] = l;
    sp(v.w, h, l); H[i*4+3] = h; L[i*4+3] = l;
}

// ======================= launch =======================
extern "C" void kernel_launch(void* const* d_in, const int* in_sizes, int n_in,
                              void* d_out, int out_size)
{
    const float* x   = (const float*)d_in[0];
    const float* qa  = (const float*)d_in[1];
    const float* ka  = (const float*)d_in[2];
    const int*   adj = (const int*)d_in[3];
    const float* mc  = (const float*)d_in[4];
    const float* Wq  = (const float*)d_in[5];
    const float* bq  = (const float*)d_in[6];
    const float* Wk  = (const float*)d_in[7];
    const float* bk  = (const float*)d_in[8];
    const float* Wv  = (const float*)d_in[9];
    const float* bv  = (const float*)d_in[10];
    const float* thr = (const float*)d_in[11];
    float* out = (float*)d_out;

    long nx4 = (long)BSZ*SEQ*DM/4;    // 2097152
    long nw4 = (long)DM*DM/4;         // 65536
    long na4 = (long)BSZ*SEQ*DAUX/4;  // 262144

    split_sel<<<(unsigned)((nx4+255)/256), 256>>>(0, x,  nx4);
    split_sel<<<(unsigned)((nw4+255)/256), 256>>>(1, Wq, nw4);
    split_sel<<<(unsigned)((nw4+255)/256), 256>>>(2, Wk, nw4);
    split_sel<<<(unsigned)((nw4+255)/256), 256>>>(3, Wv, nw4);
    split_sel<<<(unsigned)((na4+255)/256), 256>>>(4, qa, na4);
    split_sel<<<(unsigned)((na4+255)/256), 256>>>(5, ka, na4);

    qkv_mma   <<<dim3(DM/128, (BSZ*SEQ)/128, 3), 256>>>(bq, bk, bv);
    scores_mma<<<dim3(SEQ/128, SEQ/128, BSZ),    256>>>(adj, mc, thr);
    softmax_kernel<<<BSZ*SEQ, 256>>>();
    av_mma    <<<dim3(DM/128, SEQ/128, BSZ),     256>>>(out);
}

// round 8
// speedup vs baseline: 2.9446x; 1.3948x over previous
#include <cuda_runtime.h>
#include <cuda_fp16.h>
#include <math.h>
#include <stdint.h>

#define BSZ  8
#define SEQ  2048
#define DM   512
#define DAUX 64
#define NEG_HUGE (-3.402823466e38f)
#define INV_S  0.044194173824159216f
#define INV_SA 0.125f

typedef __half hf;

// smem tile geometry: rows of 16 fp16 (32B data) padded to 48B
#define ROWB 48
#define OPSZ (128*ROWB)        // 6144 B per operand tile
#define STAGE (4*OPSZ)         // Ah, Al, Bh, Bl (2 stages = 48KB)

// av kernel layout: A(P) 128x48B + B(V) 16 rows x 272B
#define BROWB 272
#define BOP (16*BROWB)
#define AVSTG (OPSZ + BOP)

// -------- static scratch --------
__device__ hf g_xh [(size_t)BSZ*SEQ*DM];
__device__ hf g_xl [(size_t)BSZ*SEQ*DM];
__device__ hf g_Wh [3][DM*DM];
__device__ hf g_Wl [3][DM*DM];
__device__ hf g_qh [(size_t)BSZ*SEQ*DM];
__device__ hf g_ql [(size_t)BSZ*SEQ*DM];
__device__ hf g_kh [(size_t)BSZ*SEQ*DM];
__device__ hf g_kl [(size_t)BSZ*SEQ*DM];
__device__ hf g_v  [(size_t)BSZ*SEQ*DM];    // [b][m][d] natural layout
__device__ hf g_qah[(size_t)BSZ*SEQ*DAUX];
__device__ hf g_kah[(size_t)BSZ*SEQ*DAUX];
__device__ float g_s[(size_t)BSZ*SEQ*SEQ];
__device__ hf g_p  [(size_t)BSZ*SEQ*SEQ];

// -------- helpers --------
__device__ __forceinline__ uint32_t s2u(const void* p){
    uint32_t a;
    asm("{ .reg .u64 t; cvta.to.shared.u64 t, %1; cvt.u32.u64 %0, t; }" : "=r"(a) : "l"(p));
    return a;
}
__device__ __forceinline__ void cp16(uint32_t d, const void* g){
    asm volatile("cp.async.cg.shared.global [%0], [%1], 16;" :: "r"(d), "l"(g) : "memory");
}
#define CP_COMMIT() asm volatile("cp.async.commit_group;" ::: "memory")
#define CP_WAIT0()  asm volatile("cp.async.wait_group 0;" ::: "memory")
#define CP_WAIT1()  asm volatile("cp.async.wait_group 1;" ::: "memory")

__device__ __forceinline__ void ldmx4(uint32_t* r, uint32_t a){
    asm volatile("ldmatrix.sync.aligned.m8n8.x4.shared.b16 {%0,%1,%2,%3}, [%4];"
        : "=r"(r[0]), "=r"(r[1]), "=r"(r[2]), "=r"(r[3]) : "r"(a));
}
__device__ __forceinline__ void ldmx4t(uint32_t* r, uint32_t a){
    asm volatile("ldmatrix.sync.aligned.m8n8.x4.trans.shared.b16 {%0,%1,%2,%3}, [%4];"
        : "=r"(r[0]), "=r"(r[1]), "=r"(r[2]), "=r"(r[3]) : "r"(a));
}
__device__ __forceinline__ void mma16816(float* d, const uint32_t* a, uint32_t b0, uint32_t b1){
    asm volatile(
        "mma.sync.aligned.m16n8k16.row.col.f32.f16.f16.f32 "
        "{%0,%1,%2,%3}, {%4,%5,%6,%7}, {%8,%9}, {%0,%1,%2,%3};"
        : "+f"(d[0]), "+f"(d[1]), "+f"(d[2]), "+f"(d[3])
        : "r"(a[0]), "r"(a[1]), "r"(a[2]), "r"(a[3]), "r"(b0), "r"(b1));
}
__device__ __forceinline__ void sp(float v, hf& h, hf& l){
    h = __float2half(v);
    l = __float2half(v - __half2float(h));
}

// load one K=16 chunk of 4 operand tiles (Ah, Al, Bh, Bl), 128 rows each
__device__ __forceinline__ void load_chunk(uint32_t stg,
    const hf* __restrict__ Ah, const hf* __restrict__ Al,
    const hf* __restrict__ Bh, const hf* __restrict__ Bl,
    long ld, long koff, int tid)
{
    int r = (tid >> 1) & 127;
    int j = tid & 1;
    long so = (long)r*ld + koff + j*8;
    uint32_t dof = (uint32_t)(r*ROWB + j*16);
    cp16(stg + 0*OPSZ + dof, Ah + so);
    cp16(stg + 1*OPSZ + dof, Al + so);
    cp16(stg + 2*OPSZ + dof, Bh + so);
    cp16(stg + 3*OPSZ + dof, Bl + so);
}
// load one K=16 chunk of 2 operand tiles (A->slot0, B->slot2)
__device__ __forceinline__ void load_chunk2(uint32_t stg,
    const hf* __restrict__ A, const hf* __restrict__ B,
    long ld, long koff, int tid)
{
    int r = (tid >> 1) & 127;
    int j = tid & 1;
    long so = (long)r*ld + koff + j*8;
    uint32_t dof = (uint32_t)(r*ROWB + j*16);
    cp16(stg + 0*OPSZ + dof, A + so);
    cp16(stg + 2*OPSZ + dof, B + so);
}

// one K=16 chunk of 3-pass split MMA; warp tile 32(M) x 64(N)
__device__ __forceinline__ void do_chunk(uint32_t stg, float (*acc)[8][4],
                                         int lane, int wm, int wn)
{
    uint32_t ah[2][4], al[2][4], bh[4][4], bl[4][4];
    int arow = lane & 15, asel = (lane >> 4) * 16;
    #pragma unroll
    for (int i = 0; i < 2; i++) {
        uint32_t ra = stg + (wm*32 + i*16 + arow)*ROWB + asel;
        ldmx4(ah[i], ra);
        ldmx4(al[i], ra + OPSZ);
    }
    int brow = ((lane >> 4) << 3) + (lane & 7), bsel = ((lane >> 3) & 1) * 16;
    #pragma unroll
    for (int jt = 0; jt < 4; jt++) {
        uint32_t rb = stg + 2*OPSZ + (wn*64 + jt*16 + brow)*ROWB + bsel;
        ldmx4(bh[jt], rb);
        ldmx4(bl[jt], rb + OPSZ);
    }
    #pragma unroll
    for (int i = 0; i < 2; i++)
        #pragma unroll
        for (int j = 0; j < 8; j++) {
            int jt = j >> 1, o = (j & 1) * 2;
            mma16816(acc[i][j], ah[i], bh[jt][o], bh[jt][o+1]);
            mma16816(acc[i][j], ah[i], bl[jt][o], bl[jt][o+1]);
            mma16816(acc[i][j], al[i], bh[jt][o], bh[jt][o+1]);
        }
}

// one K=16 chunk of single-pass MMA (A slot0, B slot2)
__device__ __forceinline__ void do_chunk1(uint32_t stg, float (*acc)[8][4],
                                          int lane, int wm, int wn)
{
    uint32_t ah[2][4], bh[4][4];
    int arow = lane & 15, asel = (lane >> 4) * 16;
    #pragma unroll
    for (int i = 0; i < 2; i++)
        ldmx4(ah[i], stg + (wm*32 + i*16 + arow)*ROWB + asel);
    int brow = ((lane >> 4) << 3) + (lane & 7), bsel = ((lane >> 3) & 1) * 16;
    #pragma unroll
    for (int jt = 0; jt < 4; jt++)
        ldmx4(bh[jt], stg + 2*OPSZ + (wn*64 + jt*16 + brow)*ROWB + bsel);
    #pragma unroll
    for (int i = 0; i < 2; i++)
        #pragma unroll
        for (int j = 0; j < 8; j++) {
            int jt = j >> 1, o = (j & 1) * 2;
            mma16816(acc[i][j], ah[i], bh[jt][o], bh[jt][o+1]);
        }
}

// ======================= QKV =======================
// grid (DM/128=4, 16384/128=128, 3), 256 thr
__global__ __launch_bounds__(256, 1) void qkv_mma(
    const float* __restrict__ bq, const float* __restrict__ bk,
    const float* __restrict__ bv)
{
    __shared__ __align__(16) unsigned char smem[2*STAGE];
    uint32_t sb = s2u(smem);
    int tid = threadIdx.x, lane = tid & 31, w = tid >> 5, wm = w & 3, wn = w >> 2;
    const int z = blockIdx.z, m0 = blockIdx.y*128, n0 = blockIdx.x*128;
    const hf *Ah = g_xh + (size_t)m0*DM, *Al = g_xl + (size_t)m0*DM;
    const hf *Bh = g_Wh[z] + (size_t)n0*DM, *Bl = g_Wl[z] + (size_t)n0*DM;

    float acc[2][8][4] = {};
    load_chunk(sb, Ah, Al, Bh, Bl, DM, 0, tid); CP_COMMIT();
    for (int c = 0; c < 32; c++) {
        int s = c & 1;
        if (c + 1 < 32) {
            load_chunk(sb + (s^1)*STAGE, Ah, Al, Bh, Bl, DM, (long)(c+1)*16, tid);
            CP_COMMIT(); CP_WAIT1();
        } else CP_WAIT0();
        __syncthreads();
        do_chunk(sb + s*STAGE, acc, lane, wm, wn);
        __syncthreads();
    }

    const float* bias = (z==0) ? bq : (z==1) ? bk : bv;
    #pragma unroll
    for (int i = 0; i < 2; i++)
        #pragma unroll
        for (int j = 0; j < 8; j++)
            #pragma unroll
            for (int e2 = 0; e2 < 2; e2++) {
                int row = m0 + wm*32 + i*16 + (lane>>2) + e2*8;
                int col = n0 + wn*64 + j*8 + ((lane&3)<<1);
                float v0 = acc[i][j][e2*2+0] + bias[col];
                float v1 = acc[i][j][e2*2+1] + bias[col+1];
                size_t t = (size_t)row*DM + col;
                if (z == 2) {
                    *(__half2*)&g_v[t] = __halves2half2(__float2half(v0), __float2half(v1));
                } else {
                    hf h0, l0, h1, l1;
                    sp(v0, h0, l0); sp(v1, h1, l1);
                    if (z == 0) {
                        *(__half2*)&g_qh[t] = __halves2half2(h0, h1);
                        *(__half2*)&g_ql[t] = __halves2half2(l0, l1);
                    } else {
                        *(__half2*)&g_kh[t] = __halves2half2(h0, h1);
                        *(__half2*)&g_kl[t] = __halves2half2(l0, l1);
                    }
                }
            }
}

// ======================= scores + merge + mask =======================
// grid (SEQ/128=16, SEQ/128=16, BSZ)
__global__ __launch_bounds__(256, 1) void scores_mma(
    const int* __restrict__ adj,
    const float* __restrict__ pmc, const float* __restrict__ pthr)
{
    __shared__ __align__(16) unsigned char smem[2*STAGE];
    uint32_t sb = s2u(smem);
    int tid = threadIdx.x, lane = tid & 31, w = tid >> 5, wm = w & 3, wn = w >> 2;
    const int b = blockIdx.z, q0 = blockIdx.y*128, c0 = blockIdx.x*128;

    const hf *Qh = g_qh + ((size_t)b*SEQ + q0)*DM, *Ql = g_ql + ((size_t)b*SEQ + q0)*DM;
    const hf *Kh = g_kh + ((size_t)b*SEQ + c0)*DM, *Kl = g_kl + ((size_t)b*SEQ + c0)*DM;
    const hf *QA = g_qah + ((size_t)b*SEQ + q0)*DAUX;
    const hf *KA = g_kah + ((size_t)b*SEQ + c0)*DAUX;

    float acc[2][8][4] = {};
    float acx[2][8][4] = {};

    const int NC = 36;  // 32 main (3-pass) + 4 aux (1-pass)
    load_chunk(sb, Qh, Ql, Kh, Kl, DM, 0, tid); CP_COMMIT();
    for (int c = 0; c < NC; c++) {
        int s = c & 1;
        if (c + 1 < NC) {
            int n = c + 1;
            if (n < 32)
                load_chunk(sb + (s^1)*STAGE, Qh, Ql, Kh, Kl, DM, (long)n*16, tid);
            else
                load_chunk2(sb + (s^1)*STAGE, QA, KA, DAUX, (long)(n-32)*16, tid);
            CP_COMMIT(); CP_WAIT1();
        } else CP_WAIT0();
        __syncthreads();
        if (c < 32) do_chunk (sb + s*STAGE, acc, lane, wm, wn);
        else        do_chunk1(sb + s*STAGE, acx, lane, wm, wn);
        __syncthreads();
    }

    const float mc = *pmc, thr = *pthr;
    #pragma unroll
    for (int i = 0; i < 2; i++)
        #pragma unroll
        for (int j = 0; j < 8; j++)
            #pragma unroll
            for (int e = 0; e < 4; e++) {
                int n = q0 + wm*32 + i*16 + (lane>>2) + ((e>>1)<<3);
                int m = c0 + wn*64 + j*8 + ((lane&3)<<1) + (e&1);
                float sv = acc[i][j][e] * INV_S;
                float sa = acx[i][j][e] * INV_SA;
                if ((sa != 0.0f) && (sv > thr)) sv = (1.0f - mc)*sv + mc*sa;
                size_t idx = ((size_t)b*SEQ + n)*SEQ + m;
                if (adj[idx] == 0) sv = NEG_HUGE;
                g_s[idx] = sv;
            }
}

// ======================= AV (1-pass fp16, trans-B) =======================
// grid (DM/128=4, SEQ/128=16, BSZ)
__global__ __launch_bounds__(256, 1) void av_mma(float* __restrict__ out)
{
    __shared__ __align__(16) unsigned char smem[2*AVSTG];
    uint32_t sb = s2u(smem);
    int tid = threadIdx.x, lane = tid & 31, w = tid >> 5, wm = w & 3, wn = w >> 2;
    const int b = blockIdx.z, n0 = blockIdx.y*128, d0 = blockIdx.x*128;

    const hf *Ap = g_p + ((size_t)b*SEQ + n0)*SEQ;
    const hf *Vp = g_v + (size_t)b*SEQ*DM + d0;

    // loaders
    int ar = (tid >> 1) & 127, aj = tid & 1;
    int br = tid >> 4,        bj = tid & 15;

    float acc[2][8][4] = {};
    const int NC = SEQ/16;  // 128

    // prologue
    cp16(sb + ar*ROWB + aj*16, Ap + (long)ar*SEQ + aj*8);
    cp16(sb + OPSZ + br*BROWB + bj*16, Vp + (size_t)br*DM + bj*8);
    CP_COMMIT();

    for (int c = 0; c < NC; c++) {
        int s = c & 1;
        if (c + 1 < NC) {
            uint32_t st2 = sb + (s^1)*AVSTG;
            long k0 = (long)(c+1)*16;
            cp16(st2 + ar*ROWB + aj*16, Ap + (long)ar*SEQ + k0 + aj*8);
            cp16(st2 + OPSZ + br*BROWB + bj*16, Vp + (size_t)(k0 + br)*DM + bj*8);
            CP_COMMIT(); CP_WAIT1();
        } else CP_WAIT0();
        __syncthreads();

        uint32_t stg = sb + s*AVSTG;
        uint32_t ah[2][4], bt[4][4];
        int arow = lane & 15, asel = (lane >> 4) * 16;
        #pragma unroll
        for (int i = 0; i < 2; i++)
            ldmx4(ah[i], stg + (wm*32 + i*16 + arow)*ROWB + asel);
        int krow = lane & 15, cadd = (lane >> 4) * 8;
        #pragma unroll
        for (int jt = 0; jt < 4; jt++)
            ldmx4t(bt[jt], stg + OPSZ + krow*BROWB + (wn*64 + jt*16 + cadd)*2);
        #pragma unroll
        for (int i = 0; i < 2; i++)
            #pragma unroll
            for (int j = 0; j < 8; j++) {
                int jt = j >> 1, o = (j & 1) * 2;
                mma16816(acc[i][j], ah[i], bt[jt][o], bt[jt][o+1]);
            }
        __syncthreads();
    }

    #pragma unroll
    for (int i = 0; i < 2; i++)
        #pragma unroll
        for (int j = 0; j < 8; j++)
            #pragma unroll
            for (int e = 0; e < 4; e++) {
                int n = n0 + wm*32 + i*16 + (lane>>2) + ((e>>1)<<3);
                int d = d0 + wn*64 + j*8 + ((lane&3)<<1) + (e&1);
                out[((size_t)b*SEQ + n)*DM + d] = acc[i][j][e];
            }
}

// ======================= softmax (emits fp16 weights) ============
__global__ __launch_bounds__(256) void softmax_kernel()
{
    const size_t row = blockIdx.x;
    const float* s = g_s + row*SEQ;
    hf* p = g_p + row*SEQ;
    const int tid = threadIdx.x;

    float v[8]; float mx = -INFINITY;
    #pragma unroll
    for (int i = 0; i < 8; i++) { v[i] = s[tid + i*256]; mx = fmaxf(mx, v[i]); }
    __shared__ float red[8];
    #pragma unroll
    for (int o = 16; o; o >>= 1) mx = fmaxf(mx, __shfl_xor_sync(~0u, mx, o));
    if ((tid & 31) == 0) red[tid >> 5] = mx;
    __syncthreads();
    if (tid < 32) {
        float t = (tid < 8) ? red[tid] : -INFINITY;
        #pragma unroll
        for (int o = 4; o; o >>= 1) t = fmaxf(t, __shfl_xor_sync(~0u, t, o));
        if (tid == 0) red[0] = t;
    }
    __syncthreads();
    mx = red[0]; __syncthreads();
    float sum = 0.0f;
    #pragma unroll
    for (int i = 0; i < 8; i++) { v[i] = expf(v[i] - mx); sum += v[i]; }
    #pragma unroll
    for (int o = 16; o; o >>= 1) sum += __shfl_xor_sync(~0u, sum, o);
    if ((tid & 31) == 0) red[tid >> 5] = sum;
    __syncthreads();
    if (tid < 32) {
        float t = (tid < 8) ? red[tid] : 0.0f;
        #pragma unroll
        for (int o = 4; o; o >>= 1) t += __shfl_xor_sync(~0u, t, o);
        if (tid == 0) red[0] = t;
    }
    __syncthreads();
    const float inv = 1.0f / red[0];
    #pragma unroll
    for (int i = 0; i < 8; i++)
        p[tid + i*256] = __float2half(v[i] * inv);
}

// ======================= prep: fp32 -> fp16 (split or single) ============
// which: 0=x (split), 1..3=Wq/Wk/Wv (split), 4=query_aux (single), 5=key_aux (single)
__global__ __launch_bounds__(256) void split_sel(int which,
    const float* __restrict__ src, long n4)
{
    long i = (long)blockIdx.x*256 + threadIdx.x;
    if (i >= n4) return;
    float4 v = ((const float4*)src)[i];
    if (which >= 4) {
        hf* H = (which == 4) ? g_qah : g_kah;
        H[i*4+0] = __float2half(v.x);
        H[i*4+1] = __float2half(v.y);
        H[i*4+2] = __float2half(v.z);
        H[i*4+3] = __float2half(v.w);
        return;
    }
    hf *H, *L;
    switch (which) {
        case 0: H = g_xh;    L = g_xl;    break;
        case 1: H = g_Wh[0]; L = g_Wl[0]; break;
        case 2: H = g_Wh[1]; L = g_Wl[1]; break;
        default: H = g_Wh[2]; L = g_Wl[2]; break;
    }
    hf h, l;
    sp(v.x, h, l); H[i*4+0] = h; L[i*4+0] = l;
    sp(v.y, h, l); H[i*4+1] = h; L[i*4+1] = l;
    sp(v.z, h, l); H[i*4+2] = h; L[i*4+2] = l;
    sp(v.w, h, l); H[i*4+3] = h; L[i*4+3] = l;
}

// ======================= launch =======================
extern "C" void kernel_launch(void* const* d_in, const int* in_sizes, int n_in,
                              void* d_out, int out_size)
{
    const float* x   = (const float*)d_in[0];
    const float* qa  = (const float*)d_in[1];
    const float* ka  = (const float*)d_in[2];
    const int*   adj = (const int*)d_in[3];
    const float* mc  = (const float*)d_in[4];
    const float* Wq  = (const float*)d_in[5];
    const float* bq  = (const float*)d_in[6];
    const float* Wk  = (const float*)d_in[7];
    const float* bk  = (const float*)d_in[8];
    const float* Wv  = (const float*)d_in[9];
    const float* bv  = (const float*)d_in[10];
    const float* thr = (const float*)d_in[11];
    float* out = (float*)d_out;

    long nx4 = (long)BSZ*SEQ*DM/4;
    long nw4 = (long)DM*DM/4;
    long na4 = (long)BSZ*SEQ*DAUX/4;

    split_sel<<<(unsigned)((nx4+255)/256), 256>>>(0, x,  nx4);
    split_sel<<<(unsigned)((nw4+255)/256), 256>>>(1, Wq, nw4);
    split_sel<<<(unsigned)((nw4+255)/256), 256>>>(2, Wk, nw4);
    split_sel<<<(unsigned)((nw4+255)/256), 256>>>(3, Wv, nw4);
    split_sel<<<(unsigned)((na4+255)/256), 256>>>(4, qa, na4);
    split_sel<<<(unsigned)((na4+255)/256), 256>>>(5, ka, na4);

    qkv_mma   <<<dim3(DM/128, (BSZ*SEQ)/128, 3), 256>>>(bq, bk, bv);
    scores_mma<<<dim3(SEQ/128, SEQ/128, BSZ),    256>>>(adj, mc, thr);
    softmax_kernel<<<BSZ*SEQ, 256>>>();
    av_mma    <<<dim3(DM/128, SEQ/128, BSZ),     256>>>(out);
}

// round 9
// speedup vs baseline: 3.3831x; 1.1489x over previous
#include <cuda_runtime.h>
#include <cuda_fp16.h>
#include <math.h>
#include <stdint.h>

#define BSZ  8
#define SEQ  2048
#define DM   512
#define DAUX 64
#define NEG_HUGE (-3.402823466e38f)
#define INV_S  0.044194173824159216f
#define INV_SA 0.125f

typedef __half hf;

// smem tile geometry: rows of 16 fp16 (32B data) padded to 48B
#define ROWB 48
#define OPSZ (128*ROWB)        // 6144 B per operand tile
#define STAGE (4*OPSZ)         // Ah, Al, Bh, Bl (2 stages = 48KB)

// av kernel layout: A(P) 128x48B + B(V) 16 rows x 272B
#define BROWB 272
#define BOP (16*BROWB)
#define AVSTG (OPSZ + BOP)

// -------- static scratch --------
__device__ hf g_xh [(size_t)BSZ*SEQ*DM];
__device__ hf g_xl [(size_t)BSZ*SEQ*DM];
__device__ hf g_Wh [3][DM*DM];
__device__ hf g_Wl [3][DM*DM];
__device__ hf g_qh [(size_t)BSZ*SEQ*DM];
__device__ hf g_ql [(size_t)BSZ*SEQ*DM];
__device__ hf g_kh [(size_t)BSZ*SEQ*DM];
__device__ hf g_kl [(size_t)BSZ*SEQ*DM];
__device__ hf g_v  [(size_t)BSZ*SEQ*DM];    // [b][m][d] natural layout
__device__ hf g_qah[(size_t)BSZ*SEQ*DAUX];
__device__ hf g_kah[(size_t)BSZ*SEQ*DAUX];
__device__ float g_s [(size_t)BSZ*SEQ*SEQ];
__device__ float g_sa[(size_t)BSZ*SEQ*SEQ];  // scaled aux scores
__device__ hf g_p  [(size_t)BSZ*SEQ*SEQ];

// -------- helpers --------
__device__ __forceinline__ uint32_t s2u(const void* p){
    uint32_t a;
    asm("{ .reg .u64 t; cvta.to.shared.u64 t, %1; cvt.u32.u64 %0, t; }" : "=r"(a) : "l"(p));
    return a;
}
__device__ __forceinline__ void cp16(uint32_t d, const void* g){
    asm volatile("cp.async.cg.shared.global [%0], [%1], 16;" :: "r"(d), "l"(g) : "memory");
}
#define CP_COMMIT() asm volatile("cp.async.commit_group;" ::: "memory")
#define CP_WAIT0()  asm volatile("cp.async.wait_group 0;" ::: "memory")
#define CP_WAIT1()  asm volatile("cp.async.wait_group 1;" ::: "memory")

__device__ __forceinline__ void ldmx4(uint32_t* r, uint32_t a){
    asm volatile("ldmatrix.sync.aligned.m8n8.x4.shared.b16 {%0,%1,%2,%3}, [%4];"
        : "=r"(r[0]), "=r"(r[1]), "=r"(r[2]), "=r"(r[3]) : "r"(a));
}
__device__ __forceinline__ void ldmx4t(uint32_t* r, uint32_t a){
    asm volatile("ldmatrix.sync.aligned.m8n8.x4.trans.shared.b16 {%0,%1,%2,%3}, [%4];"
        : "=r"(r[0]), "=r"(r[1]), "=r"(r[2]), "=r"(r[3]) : "r"(a));
}
__device__ __forceinline__ void mma16816(float* d, const uint32_t* a, uint32_t b0, uint32_t b1){
    asm volatile(
        "mma.sync.aligned.m16n8k16.row.col.f32.f16.f16.f32 "
        "{%0,%1,%2,%3}, {%4,%5,%6,%7}, {%8,%9}, {%0,%1,%2,%3};"
        : "+f"(d[0]), "+f"(d[1]), "+f"(d[2]), "+f"(d[3])
        : "r"(a[0]), "r"(a[1]), "r"(a[2]), "r"(a[3]), "r"(b0), "r"(b1));
}
__device__ __forceinline__ void sp(float v, hf& h, hf& l){
    h = __float2half(v);
    l = __float2half(v - __half2float(h));
}

// load one K=16 chunk of 4 operand tiles (Ah, Al, Bh, Bl), 128 rows each
__device__ __forceinline__ void load_chunk(uint32_t stg,
    const hf* __restrict__ Ah, const hf* __restrict__ Al,
    const hf* __restrict__ Bh, const hf* __restrict__ Bl,
    long ld, long koff, int tid)
{
    int r = (tid >> 1) & 127;
    int j = tid & 1;
    long so = (long)r*ld + koff + j*8;
    uint32_t dof = (uint32_t)(r*ROWB + j*16);
    cp16(stg + 0*OPSZ + dof, Ah + so);
    cp16(stg + 1*OPSZ + dof, Al + so);
    cp16(stg + 2*OPSZ + dof, Bh + so);
    cp16(stg + 3*OPSZ + dof, Bl + so);
}
// load one K=16 chunk of 2 operand tiles (A->slot0, B->slot2)
__device__ __forceinline__ void load_chunk2(uint32_t stg,
    const hf* __restrict__ A, const hf* __restrict__ B,
    long ld, long koff, int tid)
{
    int r = (tid >> 1) & 127;
    int j = tid & 1;
    long so = (long)r*ld + koff + j*8;
    uint32_t dof = (uint32_t)(r*ROWB + j*16);
    cp16(stg + 0*OPSZ + dof, A + so);
    cp16(stg + 2*OPSZ + dof, B + so);
}

// one K=16 chunk of 3-pass split MMA; warp tile 32(M) x 64(N)
__device__ __forceinline__ void do_chunk(uint32_t stg, float (*acc)[8][4],
                                         int lane, int wm, int wn)
{
    uint32_t ah[2][4], al[2][4], bh[4][4], bl[4][4];
    int arow = lane & 15, asel = (lane >> 4) * 16;
    #pragma unroll
    for (int i = 0; i < 2; i++) {
        uint32_t ra = stg + (wm*32 + i*16 + arow)*ROWB + asel;
        ldmx4(ah[i], ra);
        ldmx4(al[i], ra + OPSZ);
    }
    int brow = ((lane >> 4) << 3) + (lane & 7), bsel = ((lane >> 3) & 1) * 16;
    #pragma unroll
    for (int jt = 0; jt < 4; jt++) {
        uint32_t rb = stg + 2*OPSZ + (wn*64 + jt*16 + brow)*ROWB + bsel;
        ldmx4(bh[jt], rb);
        ldmx4(bl[jt], rb + OPSZ);
    }
    #pragma unroll
    for (int i = 0; i < 2; i++)
        #pragma unroll
        for (int j = 0; j < 8; j++) {
            int jt = j >> 1, o = (j & 1) * 2;
            mma16816(acc[i][j], ah[i], bh[jt][o], bh[jt][o+1]);
            mma16816(acc[i][j], ah[i], bl[jt][o], bl[jt][o+1]);
            mma16816(acc[i][j], al[i], bh[jt][o], bh[jt][o+1]);
        }
}

// one K=16 chunk of single-pass MMA (A slot0, B slot2)
__device__ __forceinline__ void do_chunk1(uint32_t stg, float (*acc)[8][4],
                                          int lane, int wm, int wn)
{
    uint32_t ah[2][4], bh[4][4];
    int arow = lane & 15, asel = (lane >> 4) * 16;
    #pragma unroll
    for (int i = 0; i < 2; i++)
        ldmx4(ah[i], stg + (wm*32 + i*16 + arow)*ROWB + asel);
    int brow = ((lane >> 4) << 3) + (lane & 7), bsel = ((lane >> 3) & 1) * 16;
    #pragma unroll
    for (int jt = 0; jt < 4; jt++)
        ldmx4(bh[jt], stg + 2*OPSZ + (wn*64 + jt*16 + brow)*ROWB + bsel);
    #pragma unroll
    for (int i = 0; i < 2; i++)
        #pragma unroll
        for (int j = 0; j < 8; j++) {
            int jt = j >> 1, o = (j & 1) * 2;
            mma16816(acc[i][j], ah[i], bh[jt][o], bh[jt][o+1]);
        }
}

// ======================= QKV =======================
// grid (DM/128=4, 16384/128=128, 3), 256 thr
__global__ __launch_bounds__(256, 2) void qkv_mma(
    const float* __restrict__ bq, const float* __restrict__ bk,
    const float* __restrict__ bv)
{
    __shared__ __align__(16) unsigned char smem[2*STAGE];
    uint32_t sb = s2u(smem);
    int tid = threadIdx.x, lane = tid & 31, w = tid >> 5, wm = w & 3, wn = w >> 2;
    const int z = blockIdx.z, m0 = blockIdx.y*128, n0 = blockIdx.x*128;
    const hf *Ah = g_xh + (size_t)m0*DM, *Al = g_xl + (size_t)m0*DM;
    const hf *Bh = g_Wh[z] + (size_t)n0*DM, *Bl = g_Wl[z] + (size_t)n0*DM;

    float acc[2][8][4] = {};
    load_chunk(sb, Ah, Al, Bh, Bl, DM, 0, tid); CP_COMMIT();
    for (int c = 0; c < 32; c++) {
        int s = c & 1;
        if (c + 1 < 32) {
            load_chunk(sb + (s^1)*STAGE, Ah, Al, Bh, Bl, DM, (long)(c+1)*16, tid);
            CP_COMMIT(); CP_WAIT1();
        } else CP_WAIT0();
        __syncthreads();
        do_chunk(sb + s*STAGE, acc, lane, wm, wn);
        __syncthreads();
    }

    const float* bias = (z==0) ? bq : (z==1) ? bk : bv;
    #pragma unroll
    for (int i = 0; i < 2; i++)
        #pragma unroll
        for (int j = 0; j < 8; j++)
            #pragma unroll
            for (int e2 = 0; e2 < 2; e2++) {
                int row = m0 + wm*32 + i*16 + (lane>>2) + e2*8;
                int col = n0 + wn*64 + j*8 + ((lane&3)<<1);
                float v0 = acc[i][j][e2*2+0] + bias[col];
                float v1 = acc[i][j][e2*2+1] + bias[col+1];
                size_t t = (size_t)row*DM + col;
                if (z == 2) {
                    *(__half2*)&g_v[t] = __halves2half2(__float2half(v0), __float2half(v1));
                } else {
                    hf h0, l0, h1, l1;
                    sp(v0, h0, l0); sp(v1, h1, l1);
                    if (z == 0) {
                        *(__half2*)&g_qh[t] = __halves2half2(h0, h1);
                        *(__half2*)&g_ql[t] = __halves2half2(l0, l1);
                    } else {
                        *(__half2*)&g_kh[t] = __halves2half2(h0, h1);
                        *(__half2*)&g_kl[t] = __halves2half2(l0, l1);
                    }
                }
            }
}

// ======================= aux scores (1-pass, K=64) =======================
// grid (SEQ/128=16, SEQ/128=16, BSZ)
__global__ __launch_bounds__(256, 2) void aux_mma()
{
    __shared__ __align__(16) unsigned char smem[2*STAGE];
    uint32_t sb = s2u(smem);
    int tid = threadIdx.x, lane = tid & 31, w = tid >> 5, wm = w & 3, wn = w >> 2;
    const int b = blockIdx.z, q0 = blockIdx.y*128, c0 = blockIdx.x*128;

    const hf *QA = g_qah + ((size_t)b*SEQ + q0)*DAUX;
    const hf *KA = g_kah + ((size_t)b*SEQ + c0)*DAUX;

    float acc[2][8][4] = {};
    load_chunk2(sb, QA, KA, DAUX, 0, tid); CP_COMMIT();
    for (int c = 0; c < 4; c++) {
        int s = c & 1;
        if (c + 1 < 4) {
            load_chunk2(sb + (s^1)*STAGE, QA, KA, DAUX, (long)(c+1)*16, tid);
            CP_COMMIT(); CP_WAIT1();
        } else CP_WAIT0();
        __syncthreads();
        do_chunk1(sb + s*STAGE, acc, lane, wm, wn);
        __syncthreads();
    }

    #pragma unroll
    for (int i = 0; i < 2; i++)
        #pragma unroll
        for (int j = 0; j < 8; j++)
            #pragma unroll
            for (int e = 0; e < 4; e++) {
                int n = q0 + wm*32 + i*16 + (lane>>2) + ((e>>1)<<3);
                int m = c0 + wn*64 + j*8 + ((lane&3)<<1) + (e&1);
                g_sa[((size_t)b*SEQ + n)*SEQ + m] = acc[i][j][e] * INV_SA;
            }
}

// ======================= scores + merge + mask =======================
// grid (SEQ/128=16, SEQ/128=16, BSZ)
__global__ __launch_bounds__(256, 2) void scores_mma(
    const int* __restrict__ adj,
    const float* __restrict__ pmc, const float* __restrict__ pthr)
{
    __shared__ __align__(16) unsigned char smem[2*STAGE];
    uint32_t sb = s2u(smem);
    int tid = threadIdx.x, lane = tid & 31, w = tid >> 5, wm = w & 3, wn = w >> 2;
    const int b = blockIdx.z, q0 = blockIdx.y*128, c0 = blockIdx.x*128;

    const hf *Qh = g_qh + ((size_t)b*SEQ + q0)*DM, *Ql = g_ql + ((size_t)b*SEQ + q0)*DM;
    const hf *Kh = g_kh + ((size_t)b*SEQ + c0)*DM, *Kl = g_kl + ((size_t)b*SEQ + c0)*DM;

    float acc[2][8][4] = {};

    load_chunk(sb, Qh, Ql, Kh, Kl, DM, 0, tid); CP_COMMIT();
    for (int c = 0; c < 32; c++) {
        int s = c & 1;
        if (c + 1 < 32) {
            load_chunk(sb + (s^1)*STAGE, Qh, Ql, Kh, Kl, DM, (long)(c+1)*16, tid);
            CP_COMMIT(); CP_WAIT1();
        } else CP_WAIT0();
        __syncthreads();
        do_chunk(sb + s*STAGE, acc, lane, wm, wn);
        __syncthreads();
    }

    const float mc = *pmc, thr = *pthr;
    #pragma unroll
    for (int i = 0; i < 2; i++)
        #pragma unroll
        for (int j = 0; j < 8; j++)
            #pragma unroll
            for (int e = 0; e < 4; e++) {
                int n = q0 + wm*32 + i*16 + (lane>>2) + ((e>>1)<<3);
                int m = c0 + wn*64 + j*8 + ((lane&3)<<1) + (e&1);
                size_t idx = ((size_t)b*SEQ + n)*SEQ + m;
                float sv = acc[i][j][e] * INV_S;
                float sa = g_sa[idx];
                if ((sa != 0.0f) && (sv > thr)) sv = (1.0f - mc)*sv + mc*sa;
                if (adj[idx] == 0) sv = NEG_HUGE;
                g_s[idx] = sv;
            }
}

// ======================= AV (1-pass fp16, trans-B) =======================
// grid (DM/128=4, SEQ/128=16, BSZ)
__global__ __launch_bounds__(256, 2) void av_mma(float* __restrict__ out)
{
    __shared__ __align__(16) unsigned char smem[2*AVSTG];
    uint32_t sb = s2u(smem);
    int tid = threadIdx.x, lane = tid & 31, w = tid >> 5, wm = w & 3, wn = w >> 2;
    const int b = blockIdx.z, n0 = blockIdx.y*128, d0 = blockIdx.x*128;

    const hf *Ap = g_p + ((size_t)b*SEQ + n0)*SEQ;
    const hf *Vp = g_v + (size_t)b*SEQ*DM + d0;

    // loaders
    int ar = (tid >> 1) & 127, aj = tid & 1;
    int br = tid >> 4,        bj = tid & 15;

    float acc[2][8][4] = {};
    const int NC = SEQ/16;  // 128

    // prologue
    cp16(sb + ar*ROWB + aj*16, Ap + (long)ar*SEQ + aj*8);
    cp16(sb + OPSZ + br*BROWB + bj*16, Vp + (size_t)br*DM + bj*8);
    CP_COMMIT();

    for (int c = 0; c < NC; c++) {
        int s = c & 1;
        if (c + 1 < NC) {
            uint32_t st2 = sb + (s^1)*AVSTG;
            long k0 = (long)(c+1)*16;
            cp16(st2 + ar*ROWB + aj*16, Ap + (long)ar*SEQ + k0 + aj*8);
            cp16(st2 + OPSZ + br*BROWB + bj*16, Vp + (size_t)(k0 + br)*DM + bj*8);
            CP_COMMIT(); CP_WAIT1();
        } else CP_WAIT0();
        __syncthreads();

        uint32_t stg = sb + s*AVSTG;
        uint32_t ah[2][4], bt[4][4];
        int arow = lane & 15, asel = (lane >> 4) * 16;
        #pragma unroll
        for (int i = 0; i < 2; i++)
            ldmx4(ah[i], stg + (wm*32 + i*16 + arow)*ROWB + asel);
        int krow = lane & 15, cadd = (lane >> 4) * 8;
        #pragma unroll
        for (int jt = 0; jt < 4; jt++)
            ldmx4t(bt[jt], stg + OPSZ + krow*BROWB + (wn*64 + jt*16 + cadd)*2);
        #pragma unroll
        for (int i = 0; i < 2; i++)
            #pragma unroll
            for (int j = 0; j < 8; j++) {
                int jt = j >> 1, o = (j & 1) * 2;
                mma16816(acc[i][j], ah[i], bt[jt][o], bt[jt][o+1]);
            }
        __syncthreads();
    }

    #pragma unroll
    for (int i = 0; i < 2; i++)
        #pragma unroll
        for (int j = 0; j < 8; j++)
            #pragma unroll
            for (int e = 0; e < 4; e++) {
                int n = n0 + wm*32 + i*16 + (lane>>2) + ((e>>1)<<3);
                int d = d0 + wn*64 + j*8 + ((lane&3)<<1) + (e&1);
                out[((size_t)b*SEQ + n)*DM + d] = acc[i][j][e];
            }
}

// ======================= softmax (emits fp16 weights) ============
__global__ __launch_bounds__(256) void softmax_kernel()
{
    const size_t row = blockIdx.x;
    const float* s = g_s + row*SEQ;
    hf* p = g_p + row*SEQ;
    const int tid = threadIdx.x;

    float v[8]; float mx = -INFINITY;
    #pragma unroll
    for (int i = 0; i < 8; i++) { v[i] = s[tid + i*256]; mx = fmaxf(mx, v[i]); }
    __shared__ float red[8];
    #pragma unroll
    for (int o = 16; o; o >>= 1) mx = fmaxf(mx, __shfl_xor_sync(~0u, mx, o));
    if ((tid & 31) == 0) red[tid >> 5] = mx;
    __syncthreads();
    if (tid < 32) {
        float t = (tid < 8) ? red[tid] : -INFINITY;
        #pragma unroll
        for (int o = 4; o; o >>= 1) t = fmaxf(t, __shfl_xor_sync(~0u, t, o));
        if (tid == 0) red[0] = t;
    }
    __syncthreads();
    mx = red[0]; __syncthreads();
    float sum = 0.0f;
    #pragma unroll
    for (int i = 0; i < 8; i++) { v[i] = expf(v[i] - mx); sum += v[i]; }
    #pragma unroll
    for (int o = 16; o; o >>= 1) sum += __shfl_xor_sync(~0u, sum, o);
    if ((tid & 31) == 0) red[tid >> 5] = sum;
    __syncthreads();
    if (tid < 32) {
        float t = (tid < 8) ? red[tid] : 0.0f;
        #pragma unroll
        for (int o = 4; o; o >>= 1) t += __shfl_xor_sync(~0u, t, o);
        if (tid == 0) red[0] = t;
    }
    __syncthreads();
    const float inv = 1.0f / red[0];
    #pragma unroll
    for (int i = 0; i < 8; i++)
        p[tid + i*256] = __float2half(v[i] * inv);
}

// ======================= prep kernels ============
// x: split into g_xh/g_xl
__global__ __launch_bounds__(256) void split_x(const float* __restrict__ src, long n4)
{
    long i = (long)blockIdx.x*256 + threadIdx.x;
    if (i >= n4) return;
    float4 v = ((const float4*)src)[i];
    hf h, l;
    sp(v.x, h, l); g_xh[i*4+0] = h; g_xl[i*4+0] = l;
    sp(v.y, h, l); g_xh[i*4+1] = h; g_xl[i*4+1] = l;
    sp(v.z, h, l); g_xh[i*4+2] = h; g_xl[i*4+2] = l;
    sp(v.w, h, l); g_xh[i*4+3] = h; g_xl[i*4+3] = l;
}
// all 3 weights: grid.y selects
__global__ __launch_bounds__(256) void split_W(
    const float* __restrict__ Wq, const float* __restrict__ Wk,
    const float* __restrict__ Wv, long n4)
{
    long i = (long)blockIdx.x*256 + threadIdx.x;
    if (i >= n4) return;
    int z = blockIdx.y;
    const float* src = (z==0) ? Wq : (z==1) ? Wk : Wv;
    hf *H = g_Wh[z], *L = g_Wl[z];
    float4 v = ((const float4*)src)[i];
    hf h, l;
    sp(v.x, h, l); H[i*4+0] = h; L[i*4+0] = l;
    sp(v.y, h, l); H[i*4+1] = h; L[i*4+1] = l;
    sp(v.z, h, l); H[i*4+2] = h; L[i*4+2] = l;
    sp(v.w, h, l); H[i*4+3] = h; L[i*4+3] = l;
}
// aux tensors (single fp16): grid.y selects qa/ka
__global__ __launch_bounds__(256) void split_aux(
    const float* __restrict__ qa, const float* __restrict__ ka, long n4)
{
    long i = (long)blockIdx.x*256 + threadIdx.x;
    if (i >= n4) return;
    const float* src = blockIdx.y ? ka : qa;
    hf* H = blockIdx.y ? g_kah : g_qah;
    float4 v = ((const float4*)src)[i];
    H[i*4+0] = __float2half(v.x);
    H[i*4+1] = __float2half(v.y);
    H[i*4+2] = __float2half(v.z);
    H[i*4+3] = __float2half(v.w);
}

// ======================= launch =======================
// launch order (for ncu -s 5 -c 1 => captures launch index 5 = scores_mma):
// 0 split_x, 1 split_W, 2 split_aux, 3 qkv, 4 aux, 5 scores, 6 softmax, 7 av
extern "C" void kernel_launch(void* const* d_in, const int* in_sizes, int n_in,
                              void* d_out, int out_size)
{
    const float* x   = (const float*)d_in[0];
    const float* qa  = (const float*)d_in[1];
    const float* ka  = (const float*)d_in[2];
    const int*   adj = (const int*)d_in[3];
    const float* mc  = (const float*)d_in[4];
    const float* Wq  = (const float*)d_in[5];
    const float* bq  = (const float*)d_in[6];
    const float* Wk  = (const float*)d_in[7];
    const float* bk  = (const float*)d_in[8];
    const float* Wv  = (const float*)d_in[9];
    const float* bv  = (const float*)d_in[10];
    const float* thr = (const float*)d_in[11];
    float* out = (float*)d_out;

    long nx4 = (long)BSZ*SEQ*DM/4;
    long nw4 = (long)DM*DM/4;
    long na4 = (long)BSZ*SEQ*DAUX/4;

    split_x  <<<(unsigned)((nx4+255)/256), 256>>>(x, nx4);
    split_W  <<<dim3((unsigned)((nw4+255)/256), 3), 256>>>(Wq, Wk, Wv, nw4);
    split_aux<<<dim3((unsigned)((na4+255)/256), 2), 256>>>(qa, ka, na4);

    qkv_mma   <<<dim3(DM/128, (BSZ*SEQ)/128, 3), 256>>>(bq, bk, bv);
    aux_mma   <<<dim3(SEQ/128, SEQ/128, BSZ),    256>>>();
    scores_mma<<<dim3(SEQ/128, SEQ/128, BSZ),    256>>>(adj, mc, thr);
    softmax_kernel<<<BSZ*SEQ, 256>>>();
    av_mma    <<<dim3(DM/128, SEQ/128, BSZ),     256>>>(out);
}

// round 13
// speedup vs baseline: 3.8265x; 1.1311x over previous
#include <cuda_runtime.h>
#include <cuda_fp16.h>
#include <math.h>
#include <stdint.h>

#define BSZ  8
#define SEQ  2048
#define DM   512
#define DAUX 64
#define NEG_HUGE (-3.402823466e38f)
#define INV_S  0.044194173824159216f
#define INV_SA 0.125f

typedef __half hf;

// smem tile geometry: rows of 16 fp16 (32B data) padded to 48B
#define ROWB 48
#define OPSZ (128*ROWB)        // 6144 B per operand tile
#define STAGE (4*OPSZ)         // Ah, Al, Bh, Bl (2 stages = 48KB)
#define STG2  (2*OPSZ)         // compact 2-tile stage (aux)

// av kernel layout: A(P) 128x48B + B(V) 16 rows x 272B
#define BROWB 272
#define BOP (16*BROWB)
#define AVSTG (OPSZ + BOP)

// -------- static scratch --------
__device__ hf g_xh [(size_t)BSZ*SEQ*DM];
__device__ hf g_xl [(size_t)BSZ*SEQ*DM];
__device__ hf g_Wh [3][DM*DM];
__device__ hf g_Wl [3][DM*DM];
__device__ hf g_qh [(size_t)BSZ*SEQ*DM];
__device__ hf g_ql [(size_t)BSZ*SEQ*DM];
__device__ hf g_kh [(size_t)BSZ*SEQ*DM];
__device__ hf g_kl [(size_t)BSZ*SEQ*DM];
__device__ hf g_v  [(size_t)BSZ*SEQ*DM];    // [b][m][d] natural layout
__device__ hf g_qah[(size_t)BSZ*SEQ*DAUX];
__device__ hf g_kah[(size_t)BSZ*SEQ*DAUX];
__device__ float g_s [(size_t)BSZ*SEQ*SEQ];
__device__ float g_sa[(size_t)BSZ*SEQ*SEQ];  // scaled aux scores
__device__ hf g_p  [(size_t)BSZ*SEQ*SEQ];

// -------- helpers --------
__device__ __forceinline__ uint32_t s2u(const void* p){
    uint32_t a;
    asm("{ .reg .u64 t; cvta.to.shared.u64 t, %1; cvt.u32.u64 %0, t; }" : "=r"(a) : "l"(p));
    return a;
}
__device__ __forceinline__ void cp16(uint32_t d, const void* g){
    asm volatile("cp.async.cg.shared.global [%0], [%1], 16;" :: "r"(d), "l"(g) : "memory");
}
#define CP_COMMIT() asm volatile("cp.async.commit_group;" ::: "memory")
#define CP_WAIT0()  asm volatile("cp.async.wait_group 0;" ::: "memory")
#define CP_WAIT1()  asm volatile("cp.async.wait_group 1;" ::: "memory")

__device__ __forceinline__ void ldmx4(uint32_t* r, uint32_t a){
    asm volatile("ldmatrix.sync.aligned.m8n8.x4.shared.b16 {%0,%1,%2,%3}, [%4];"
        : "=r"(r[0]), "=r"(r[1]), "=r"(r[2]), "=r"(r[3]) : "r"(a));
}
__device__ __forceinline__ void ldmx4t(uint32_t* r, uint32_t a){
    asm volatile("ldmatrix.sync.aligned.m8n8.x4.trans.shared.b16 {%0,%1,%2,%3}, [%4];"
        : "=r"(r[0]), "=r"(r[1]), "=r"(r[2]), "=r"(r[3]) : "r"(a));
}
__device__ __forceinline__ void mma16816(float* d, const uint32_t* a, uint32_t b0, uint32_t b1){
    asm volatile(
        "mma.sync.aligned.m16n8k16.row.col.f32.f16.f16.f32 "
        "{%0,%1,%2,%3}, {%4,%5,%6,%7}, {%8,%9}, {%0,%1,%2,%3};"
        : "+f"(d[0]), "+f"(d[1]), "+f"(d[2]), "+f"(d[3])
        : "r"(a[0]), "r"(a[1]), "r"(a[2]), "r"(a[3]), "r"(b0), "r"(b1));
}
__device__ __forceinline__ void sp(float v, hf& h, hf& l){
    h = __float2half(v);
    l = __float2half(v - __half2float(h));
}

// load one K=16 chunk of 4 operand tiles (Ah, Al, Bh, Bl), 128 rows each
__device__ __forceinline__ void load_chunk(uint32_t stg,
    const hf* __restrict__ Ah, const hf* __restrict__ Al,
    const hf* __restrict__ Bh, const hf* __restrict__ Bl,
    long ld, long koff, int tid)
{
    int r = (tid >> 1) & 127;
    int j = tid & 1;
    long so = (long)r*ld + koff + j*8;
    uint32_t dof = (uint32_t)(r*ROWB + j*16);
    cp16(stg + 0*OPSZ + dof, Ah + so);
    cp16(stg + 1*OPSZ + dof, Al + so);
    cp16(stg + 2*OPSZ + dof, Bh + so);
    cp16(stg + 3*OPSZ + dof, Bl + so);
}
// compact: load one K=16 chunk of 2 operand tiles (A->0, B->OPSZ)
__device__ __forceinline__ void load_chunk2(uint32_t stg,
    const hf* __restrict__ A, const hf* __restrict__ B,
    long ld, long koff, int tid)
{
    int r = (tid >> 1) & 127;
    int j = tid & 1;
    long so = (long)r*ld + koff + j*8;
    uint32_t dof = (uint32_t)(r*ROWB + j*16);
    cp16(stg + dof, A + so);
    cp16(stg + OPSZ + dof, B + so);
}

// one K=16 chunk of 3-pass split MMA; warp tile 32(M) x 64(N)
__device__ __forceinline__ void do_chunk(uint32_t stg, float (*acc)[8][4],
                                         int lane, int wm, int wn)
{
    uint32_t ah[2][4], al[2][4], bh[4][4], bl[4][4];
    int arow = lane & 15, asel = (lane >> 4) * 16;
    #pragma unroll
    for (int i = 0; i < 2; i++) {
        uint32_t ra = stg + (wm*32 + i*16 + arow)*ROWB + asel;
        ldmx4(ah[i], ra);
        ldmx4(al[i], ra + OPSZ);
    }
    int brow = ((lane >> 4) << 3) + (lane & 7), bsel = ((lane >> 3) & 1) * 16;
    #pragma unroll
    for (int jt = 0; jt < 4; jt++) {
        uint32_t rb = stg + 2*OPSZ + (wn*64 + jt*16 + brow)*ROWB + bsel;
        ldmx4(bh[jt], rb);
        ldmx4(bl[jt], rb + OPSZ);
    }
    #pragma unroll
    for (int i = 0; i < 2; i++)
        #pragma unroll
        for (int j = 0; j < 8; j++) {
            int jt = j >> 1, o = (j & 1) * 2;
            mma16816(acc[i][j], ah[i], bh[jt][o], bh[jt][o+1]);
            mma16816(acc[i][j], ah[i], bl[jt][o], bl[jt][o+1]);
            mma16816(acc[i][j], al[i], bh[jt][o], bh[jt][o+1]);
        }
}

// one K=16 chunk of single-pass MMA on compact stage (A at 0, B at OPSZ)
__device__ __forceinline__ void do_chunk1c(uint32_t stg, float (*acc)[8][4],
                                           int lane, int wm, int wn)
{
    uint32_t ah[2][4], bh[4][4];
    int arow = lane & 15, asel = (lane >> 4) * 16;
    #pragma unroll
    for (int i = 0; i < 2; i++)
        ldmx4(ah[i], stg + (wm*32 + i*16 + arow)*ROWB + asel);
    int brow = ((lane >> 4) << 3) + (lane & 7), bsel = ((lane >> 3) & 1) * 16;
    #pragma unroll
    for (int jt = 0; jt < 4; jt++)
        ldmx4(bh[jt], stg + OPSZ + (wn*64 + jt*16 + brow)*ROWB + bsel);
    #pragma unroll
    for (int i = 0; i < 2; i++)
        #pragma unroll
        for (int j = 0; j < 8; j++) {
            int jt = j >> 1, o = (j & 1) * 2;
            mma16816(acc[i][j], ah[i], bh[jt][o], bh[jt][o+1]);
        }
}

// ======================= QKV =======================
// grid (DM/128=4, 16384/128=128, 3), 256 thr; 2-stage single-sync pipeline
__global__ __launch_bounds__(256, 2) void qkv_mma(
    const float* __restrict__ bq, const float* __restrict__ bk,
    const float* __restrict__ bv)
{
    __shared__ __align__(16) unsigned char smem[2*STAGE];
    uint32_t sb = s2u(smem);
    int tid = threadIdx.x, lane = tid & 31, w = tid >> 5, wm = w & 3, wn = w >> 2;
    const int z = blockIdx.z, m0 = blockIdx.y*128, n0 = blockIdx.x*128;
    const hf *Ah = g_xh + (size_t)m0*DM, *Al = g_xl + (size_t)m0*DM;
    const hf *Bh = g_Wh[z] + (size_t)n0*DM, *Bl = g_Wl[z] + (size_t)n0*DM;

    float acc[2][8][4] = {};
    load_chunk(sb, Ah, Al, Bh, Bl, DM, 0, tid); CP_COMMIT();
    for (int c = 0; c < 32; c++) {
        CP_WAIT0();
        __syncthreads();
        if (c + 1 < 32) {
            load_chunk(sb + ((c+1)&1)*STAGE, Ah, Al, Bh, Bl, DM, (long)(c+1)*16, tid);
            CP_COMMIT();
        }
        do_chunk(sb + (c&1)*STAGE, acc, lane, wm, wn);
    }

    const float* bias = (z==0) ? bq : (z==1) ? bk : bv;
    #pragma unroll
    for (int i = 0; i < 2; i++)
        #pragma unroll
        for (int j = 0; j < 8; j++)
            #pragma unroll
            for (int e2 = 0; e2 < 2; e2++) {
                int row = m0 + wm*32 + i*16 + (lane>>2) + e2*8;
                int col = n0 + wn*64 + j*8 + ((lane&3)<<1);
                float v0 = acc[i][j][e2*2+0] + bias[col];
                float v1 = acc[i][j][e2*2+1] + bias[col+1];
                size_t t = (size_t)row*DM + col;
                if (z == 2) {
                    *(__half2*)&g_v[t] = __halves2half2(__float2half(v0), __float2half(v1));
                } else {
                    hf h0, l0, h1, l1;
                    sp(v0, h0, l0); sp(v1, h1, l1);
                    if (z == 0) {
                        *(__half2*)&g_qh[t] = __halves2half2(h0, h1);
                        *(__half2*)&g_ql[t] = __halves2half2(l0, l1);
                    } else {
                        *(__half2*)&g_kh[t] = __halves2half2(h0, h1);
                        *(__half2*)&g_kl[t] = __halves2half2(l0, l1);
                    }
                }
            }
}

// ======================= aux scores (1-pass, K=64) =======================
// grid (SEQ/128=16, SEQ/128=16, BSZ); 3-stage compact pipeline
__global__ __launch_bounds__(256, 2) void aux_mma()
{
    __shared__ __align__(16) unsigned char smem[3*STG2];
    uint32_t sb = s2u(smem);
    int tid = threadIdx.x, lane = tid & 31, w = tid >> 5, wm = w & 3, wn = w >> 2;
    const int b = blockIdx.z, q0 = blockIdx.y*128, c0 = blockIdx.x*128;

    const hf *QA = g_qah + ((size_t)b*SEQ + q0)*DAUX;
    const hf *KA = g_kah + ((size_t)b*SEQ + c0)*DAUX;

    float acc[2][8][4] = {};
    load_chunk2(sb,        QA, KA, DAUX, 0,  tid); CP_COMMIT();
    load_chunk2(sb + STG2, QA, KA, DAUX, 16, tid); CP_COMMIT();
    int sld = 2, scur = 0;
    for (int c = 0; c < 4; c++) {
        // stage c's group is guaranteed complete by wait_group 1 only while a
        // younger group is also pending; last iteration must drain fully.
        if (c + 1 < 4) CP_WAIT1(); else CP_WAIT0();
        __syncthreads();
        if (c + 2 < 4) {
            load_chunk2(sb + sld*STG2, QA, KA, DAUX, (long)(c+2)*16, tid);
            CP_COMMIT();
            if (++sld == 3) sld = 0;
        }
        do_chunk1c(sb + scur*STG2, acc, lane, wm, wn);
        if (++scur == 3) scur = 0;
    }

    #pragma unroll
    for (int i = 0; i < 2; i++)
        #pragma unroll
        for (int j = 0; j < 8; j++)
            #pragma unroll
            for (int e2 = 0; e2 < 2; e2++) {
                int n = q0 + wm*32 + i*16 + (lane>>2) + e2*8;
                int m = c0 + wn*64 + j*8 + ((lane&3)<<1);
                float2 v2 = make_float2(acc[i][j][e2*2+0]*INV_SA, acc[i][j][e2*2+1]*INV_SA);
                *(float2*)&g_sa[((size_t)b*SEQ + n)*SEQ + m] = v2;
            }
}

// ======================= scores + merge + mask =======================
// grid (SEQ/128=16, SEQ/128=16, BSZ); 2-stage single-sync pipeline
__global__ __launch_bounds__(256, 2) void scores_mma(
    const int* __restrict__ adj,
    const float* __restrict__ pmc, const float* __restrict__ pthr)
{
    __shared__ __align__(16) unsigned char smem[2*STAGE];
    uint32_t sb = s2u(smem);
    int tid = threadIdx.x, lane = tid & 31, w = tid >> 5, wm = w & 3, wn = w >> 2;
    const int b = blockIdx.z, q0 = blockIdx.y*128, c0 = blockIdx.x*128;

    const hf *Qh = g_qh + ((size_t)b*SEQ + q0)*DM, *Ql = g_ql + ((size_t)b*SEQ + q0)*DM;
    const hf *Kh = g_kh + ((size_t)b*SEQ + c0)*DM, *Kl = g_kl + ((size_t)b*SEQ + c0)*DM;

    float acc[2][8][4] = {};
    load_chunk(sb, Qh, Ql, Kh, Kl, DM, 0, tid); CP_COMMIT();
    for (int c = 0; c < 32; c++) {
        CP_WAIT0();
        __syncthreads();
        if (c + 1 < 32) {
            load_chunk(sb + ((c+1)&1)*STAGE, Qh, Ql, Kh, Kl, DM, (long)(c+1)*16, tid);
            CP_COMMIT();
        }
        do_chunk(sb + (c&1)*STAGE, acc, lane, wm, wn);
    }

    const float mc = *pmc, thr = *pthr;
    #pragma unroll
    for (int i = 0; i < 2; i++)
        #pragma unroll
        for (int j = 0; j < 8; j++)
            #pragma unroll
            for (int e2 = 0; e2 < 2; e2++) {
                int n = q0 + wm*32 + i*16 + (lane>>2) + e2*8;
                int m = c0 + wn*64 + j*8 + ((lane&3)<<1);
                size_t idx = ((size_t)b*SEQ + n)*SEQ + m;
                float2 sa2 = *(const float2*)&g_sa[idx];
                int2   ad2 = *(const int2*)&adj[idx];
                float sv0 = acc[i][j][e2*2+0] * INV_S;
                float sv1 = acc[i][j][e2*2+1] * INV_S;
                if ((sa2.x != 0.0f) && (sv0 > thr)) sv0 = (1.0f - mc)*sv0 + mc*sa2.x;
                if ((sa2.y != 0.0f) && (sv1 > thr)) sv1 = (1.0f - mc)*sv1 + mc*sa2.y;
                if (ad2.x == 0) sv0 = NEG_HUGE;
                if (ad2.y == 0) sv1 = NEG_HUGE;
                *(float2*)&g_s[idx] = make_float2(sv0, sv1);
            }
}

// ======================= AV (1-pass fp16, trans-B) =======================
// grid (DM/128=4, SEQ/128=16, BSZ); 3-stage pipeline
__global__ __launch_bounds__(256, 2) void av_mma(float* __restrict__ out)
{
    __shared__ __align__(16) unsigned char smem[3*AVSTG];
    uint32_t sb = s2u(smem);
    int tid = threadIdx.x, lane = tid & 31, w = tid >> 5, wm = w & 3, wn = w >> 2;
    const int b = blockIdx.z, n0 = blockIdx.y*128, d0 = blockIdx.x*128;

    const hf *Ap = g_p + ((size_t)b*SEQ + n0)*SEQ;
    const hf *Vp = g_v + (size_t)b*SEQ*DM + d0;

    int ar = (tid >> 1) & 127, aj = tid & 1;
    int br = tid >> 4,        bj = tid & 15;

    float acc[2][8][4] = {};
    const int NC = SEQ/16;  // 128

    // prologue: stages 0, 1
    #pragma unroll
    for (int pc = 0; pc < 2; pc++) {
        uint32_t st = sb + pc*AVSTG;
        long k0 = (long)pc*16;
        cp16(st + ar*ROWB + aj*16, Ap + (long)ar*SEQ + k0 + aj*8);
        cp16(st + OPSZ + br*BROWB + bj*16, Vp + (size_t)(k0 + br)*DM + bj*8);
        CP_COMMIT();
    }

    int sld = 2, scur = 0;
    for (int c = 0; c < NC; c++) {
        // tail must fully drain: wait_group 1 is a no-op when only stage c's
        // own group remains pending.
        if (c + 1 < NC) CP_WAIT1(); else CP_WAIT0();
        __syncthreads();
        if (c + 2 < NC) {
            uint32_t st2 = sb + sld*AVSTG;
            long k0 = (long)(c+2)*16;
            cp16(st2 + ar*ROWB + aj*16, Ap + (long)ar*SEQ + k0 + aj*8);
            cp16(st2 + OPSZ + br*BROWB + bj*16, Vp + (size_t)(k0 + br)*DM + bj*8);
            CP_COMMIT();
            if (++sld == 3) sld = 0;
        }

        uint32_t stg = sb + scur*AVSTG;
        if (++scur == 3) scur = 0;
        uint32_t ah[2][4], bt[4][4];
        int arow = lane & 15, asel = (lane >> 4) * 16;
        #pragma unroll
        for (int i = 0; i < 2; i++)
            ldmx4(ah[i], stg + (wm*32 + i*16 + arow)*ROWB + asel);
        int krow = lane & 15, cadd = (lane >> 4) * 8;
        #pragma unroll
        for (int jt = 0; jt < 4; jt++)
            ldmx4t(bt[jt], stg + OPSZ + krow*BROWB + (wn*64 + jt*16 + cadd)*2);
        #pragma unroll
        for (int i = 0; i < 2; i++)
            #pragma unroll
            for (int j = 0; j < 8; j++) {
                int jt = j >> 1, o = (j & 1) * 2;
                mma16816(acc[i][j], ah[i], bt[jt][o], bt[jt][o+1]);
            }
    }

    #pragma unroll
    for (int i = 0; i < 2; i++)
        #pragma unroll
        for (int j = 0; j < 8; j++)
            #pragma unroll
            for (int e2 = 0; e2 < 2; e2++) {
                int n = n0 + wm*32 + i*16 + (lane>>2) + e2*8;
                int d = d0 + wn*64 + j*8 + ((lane&3)<<1);
                *(float2*)&out[((size_t)b*SEQ + n)*DM + d] =
                    make_float2(acc[i][j][e2*2+0], acc[i][j][e2*2+1]);
            }
}

// ======================= softmax (emits fp16 weights) ============
__global__ __launch_bounds__(256) void softmax_kernel()
{
    const size_t row = blockIdx.x;
    const float* s = g_s + row*SEQ;
    hf* p = g_p + row*SEQ;
    const int tid = threadIdx.x;

    float v[8]; float mx = -INFINITY;
    #pragma unroll
    for (int i = 0; i < 8; i++) { v[i] = s[tid + i*256]; mx = fmaxf(mx, v[i]); }
    __shared__ float red[8];
    #pragma unroll
    for (int o = 16; o; o >>= 1) mx = fmaxf(mx, __shfl_xor_sync(~0u, mx, o));
    if ((tid & 31) == 0) red[tid >> 5] = mx;
    __syncthreads();
    if (tid < 32) {
        float t = (tid < 8) ? red[tid] : -INFINITY;
        #pragma unroll
        for (int o = 4; o; o >>= 1) t = fmaxf(t, __shfl_xor_sync(~0u, t, o));
        if (tid == 0) red[0] = t;
    }
    __syncthreads();
    mx = red[0]; __syncthreads();
    float sum = 0.0f;
    #pragma unroll
    for (int i = 0; i < 8; i++) { v[i] = expf(v[i] - mx); sum += v[i]; }
    #pragma unroll
    for (int o = 16; o; o >>= 1) sum += __shfl_xor_sync(~0u, sum, o);
    if ((tid & 31) == 0) red[tid >> 5] = sum;
    __syncthreads();
    if (tid < 32) {
        float t = (tid < 8) ? red[tid] : 0.0f;
        #pragma unroll
        for (int o = 4; o; o >>= 1) t += __shfl_xor_sync(~0u, t, o);
        if (tid == 0) red[0] = t;
    }
    __syncthreads();
    const float inv = 1.0f / red[0];
    #pragma unroll
    for (int i = 0; i < 8; i++)
        p[tid + i*256] = __float2half(v[i] * inv);
}

// ======================= prep kernels ============
__global__ __launch_bounds__(256) void split_x(const float* __restrict__ src, long n4)
{
    long i = (long)blockIdx.x*256 + threadIdx.x;
    if (i >= n4) return;
    float4 v = ((const float4*)src)[i];
    hf h, l;
    sp(v.x, h, l); g_xh[i*4+0] = h; g_xl[i*4+0] = l;
    sp(v.y, h, l); g_xh[i*4+1] = h; g_xl[i*4+1] = l;
    sp(v.z, h, l); g_xh[i*4+2] = h; g_xl[i*4+2] = l;
    sp(v.w, h, l); g_xh[i*4+3] = h; g_xl[i*4+3] = l;
}
__global__ __launch_bounds__(256) void split_W(
    const float* __restrict__ Wq, const float* __restrict__ Wk,
    const float* __restrict__ Wv, long n4)
{
    long i = (long)blockIdx.x*256 + threadIdx.x;
    if (i >= n4) return;
    int z = blockIdx.y;
    const float* src = (z==0) ? Wq : (z==1) ? Wk : Wv;
    hf *H = g_Wh[z], *L = g_Wl[z];
    float4 v = ((const float4*)src)[i];
    hf h, l;
    sp(v.x, h, l); H[i*4+0] = h; L[i*4+0] = l;
    sp(v.y, h, l); H[i*4+1] = h; L[i*4+1] = l;
    sp(v.z, h, l); H[i*4+2] = h; L[i*4+2] = l;
    sp(v.w, h, l); H[i*4+3] = h; L[i*4+3] = l;
}
__global__ __launch_bounds__(256) void split_aux(
    const float* __restrict__ qa, const float* __restrict__ ka, long n4)
{
    long i = (long)blockIdx.x*256 + threadIdx.x;
    if (i >= n4) return;
    const float* src = blockIdx.y ? ka : qa;
    hf* H = blockIdx.y ? g_kah : g_qah;
    float4 v = ((const float4*)src)[i];
    H[i*4+0] = __float2half(v.x);
    H[i*4+1] = __float2half(v.y);
    H[i*4+2] = __float2half(v.z);
    H[i*4+3] = __float2half(v.w);
}

// ======================= launch =======================
// 0 split_x, 1 split_W, 2 split_aux, 3 qkv, 4 aux, 5 scores, 6 softmax, 7 av
extern "C" void kernel_launch(void* const* d_in, const int* in_sizes, int n_in,
                              void* d_out, int out_size)
{
    const float* x   = (const float*)d_in[0];
    const float* qa  = (const float*)d_in[1];
    const float* ka  = (const float*)d_in[2];
    const int*   adj = (const int*)d_in[3];
    const float* mc  = (const float*)d_in[4];
    const float* Wq  = (const float*)d_in[5];
    const float* bq  = (const float*)d_in[6];
    const float* Wk  = (const float*)d_in[7];
    const float* bk  = (const float*)d_in[8];
    const float* Wv  = (const float*)d_in[9];
    const float* bv  = (const float*)d_in[10];
    const float* thr = (const float*)d_in[11];
    float* out = (float*)d_out;

    long nx4 = (long)BSZ*SEQ*DM/4;
    long nw4 = (long)DM*DM/4;
    long na4 = (long)BSZ*SEQ*DAUX/4;

    split_x  <<<(unsigned)((nx4+255)/256), 256>>>(x, nx4);
    split_W  <<<dim3((unsigned)((nw4+255)/256), 3), 256>>>(Wq, Wk, Wv, nw4);
    split_aux<<<dim3((unsigned)((na4+255)/256), 2), 256>>>(qa, ka, na4);

    qkv_mma   <<<dim3(DM/128, (BSZ*SEQ)/128, 3), 256>>>(bq, bk, bv);
    aux_mma   <<<dim3(SEQ/128, SEQ/128, BSZ),    256>>>();
    scores_mma<<<dim3(SEQ/128, SEQ/128, BSZ),    256>>>(adj, mc, thr);
    softmax_kernel<<<BSZ*SEQ, 256>>>();
    av_mma    <<<dim3(DM/128, SEQ/128, BSZ),     256>>>(out);
}